// round 6
// baseline (speedup 1.0000x reference)
#include <cuda_runtime.h>
#include <math.h>
#include <stdint.h>

#define TT 700
#define BB 32
#define HH 800
#define K1 1600
#define DINX 53
#define GRID 148
#define NW 11
#define NTHR (NW * 32)

// ---------------- scratch (static device globals; no allocation) ----------------
__device__ float d_xT [TT * 64 * BB];         // [t][k(64 padded)][b]
__device__ float d_h0T[TT * K1 * BB];         // [t][row 0..1599][b]  f=[0,800) b=[800,1600)
__device__ float d_h1T[TT * K1 * BB];
__device__ float d_xg [2 * TT * 3200 * BB];   // [dir][t][gate-row 0..3199][b]  (bias folded)
__device__ float d_Wt0f[DINX * 3200];         // transposed Wih0: [k][row]
__device__ float d_Wt0b[DINX * 3200];
__device__ float d_Wt1f[K1 * 3200];
__device__ float d_Wt1b[K1 * 3200];
__device__ float d_dih[TT * BB * 3];

// global barrier state (zero-initialized)
__device__ unsigned g_cnt[8];
__device__ unsigned g_master;
__device__ volatile unsigned g_gen;

// ---------------- small PTX helpers ----------------
__device__ __forceinline__ uint32_t smem_u32(const void* p) {
    uint32_t a;
    asm("{ .reg .u64 t; cvta.to.shared.u64 t, %1; cvt.u32.u64 %0, t; }" : "=r"(a) : "l"(p));
    return a;
}
__device__ __forceinline__ void mbar_init(uint32_t mbar, uint32_t count) {
    asm volatile("mbarrier.init.shared.b64 [%0], %1;" :: "r"(mbar), "r"(count) : "memory");
}
__device__ __forceinline__ void mbar_expect_tx(uint32_t mbar, uint32_t bytes) {
    asm volatile("mbarrier.arrive.expect_tx.shared.b64 _, [%0], %1;" :: "r"(mbar), "r"(bytes) : "memory");
}
__device__ __forceinline__ void bulk_g2s(uint32_t dst, const void* src, uint32_t bytes, uint32_t mbar) {
    asm volatile("cp.async.bulk.shared::cluster.global.mbarrier::complete_tx::bytes [%0], [%1], %2, [%3];"
                 :: "r"(dst), "l"(src), "r"(bytes), "r"(mbar) : "memory");
}
__device__ __forceinline__ void mbar_wait(uint32_t mbar, uint32_t phase) {
    asm volatile(
        "{\n\t.reg .pred P1;\n\t"
        "W%=:\n\t"
        "mbarrier.try_wait.parity.acquire.cta.shared::cta.b64 P1, [%0], %1, 0x989680;\n\t"
        "@P1 bra D%=;\n\t"
        "bra W%=;\n\t"
        "D%=:\n\t}"
        :: "r"(mbar), "r"(phase) : "memory");
}

// ---------------- prep: x = concat(emb[primary], evolutionary), transposed ----------------
__global__ void k_prep(const int* __restrict__ primary,
                       const float* __restrict__ evo,
                       const float* __restrict__ emb)
{
    int idx = blockIdx.x * blockDim.x + threadIdx.x;
    if (idx >= TT * 64 * BB) return;
    int b = idx & 31;
    int k = (idx >> 5) & 63;
    int t = idx >> 11;
    float v = 0.f;
    if (k < 32) {
        int aa = primary[t * BB + b];
        v = emb[aa * 32 + k];
    } else if (k < DINX) {
        v = evo[(t * BB + b) * 21 + (k - 32)];
    }
    d_xT[idx] = v;
}

// ---------------- transpose input weights into [k][row] ----------------
__global__ void k_trans(const float* __restrict__ W0f, const float* __restrict__ W0b,
                        const float* __restrict__ W1f, const float* __restrict__ W1b)
{
    const int N0 = 3200 * DINX;
    const int N1 = 3200 * K1;
    const int NT = 2 * N0 + 2 * N1;
    for (int i = blockIdx.x * blockDim.x + threadIdx.x; i < NT; i += gridDim.x * blockDim.x) {
        if (i < N0) {
            int r = i / DINX, k = i % DINX;
            d_Wt0f[k * 3200 + r] = W0f[i];
        } else if (i < 2 * N0) {
            int j = i - N0;
            int r = j / DINX, k = j % DINX;
            d_Wt0b[k * 3200 + r] = W0b[j];
        } else if (i < 2 * N0 + N1) {
            int j = i - 2 * N0;
            int r = j / K1, k = j % K1;
            d_Wt1f[(size_t)k * 3200 + r] = W1f[j];
        } else {
            int j = i - 2 * N0 - N1;
            int r = j / K1, k = j % K1;
            d_Wt1b[(size_t)k * 3200 + r] = W1b[j];
        }
    }
}

// ---------------- xg precompute: xg[dir][t][r][b] = bias[r] + sum_k Wt[k][r] * src[t][k][b] ----------------
template <int KK, int SSTR, int LAYER>
__global__ void k_xg(const float* __restrict__ bF, const float* __restrict__ bB)
{
    extern __shared__ float sx[];   // KK * 32 floats
    const int t = blockIdx.x;
    const int dir = blockIdx.y;
    const float* Wt   = (LAYER == 0) ? (dir ? d_Wt0b : d_Wt0f) : (dir ? d_Wt1b : d_Wt1f);
    const float* bias = dir ? bB : bF;
    const float* src  = (LAYER == 0) ? d_xT : d_h0T;
    const float* s0 = src + (size_t)t * SSTR * BB;

    for (int i = threadIdx.x; i < KK * BB / 4; i += blockDim.x)
        ((float4*)sx)[i] = ((const float4*)s0)[i];
    __syncthreads();

    float* out = d_xg + (size_t)(dir * TT + t) * 3200 * BB;
    for (int r = threadIdx.x; r < 3200; r += blockDim.x) {
        float acc[32];
        #pragma unroll
        for (int j = 0; j < 32; j++) acc[j] = 0.f;
        const float* wp = Wt + r;
        for (int k = 0; k < KK; k++) {
            float w = wp[(size_t)k * 3200];
            const float4* xv = (const float4*)(sx + k * 32);
            #pragma unroll
            for (int j = 0; j < 8; j++) {
                float4 v = xv[j];
                acc[4 * j + 0] = fmaf(w, v.x, acc[4 * j + 0]);
                acc[4 * j + 1] = fmaf(w, v.y, acc[4 * j + 1]);
                acc[4 * j + 2] = fmaf(w, v.z, acc[4 * j + 2]);
                acc[4 * j + 3] = fmaf(w, v.w, acc[4 * j + 3]);
            }
        }
        float bv = bias[r];
        float4* op = (float4*)(out + (size_t)r * BB);
        #pragma unroll
        for (int j = 0; j < 8; j++) {
            float4 v4;
            v4.x = acc[4 * j + 0] + bv;
            v4.y = acc[4 * j + 1] + bv;
            v4.z = acc[4 * j + 2] + bv;
            v4.w = acc[4 * j + 3] + bv;
            op[j] = v4;
        }
    }
}

// ---------------- hierarchical grid-wide barrier ----------------
__device__ __forceinline__ void gsync(unsigned& mygen)
{
    __syncthreads();
    if (threadIdx.x == 0) {
        __threadfence();
        int grp = blockIdx.x & 7;
        unsigned sz = (grp < 4) ? 19u : 18u;   // 148 = 4*19 + 4*18
        unsigned v = atomicAdd(&g_cnt[grp], 1u);
        if (v == sz - 1u) {
            g_cnt[grp] = 0u;
            __threadfence();
            unsigned m = atomicAdd(&g_master, 1u);
            if (m == 7u) {
                g_master = 0u;
                __threadfence();
                g_gen = mygen + 1u;
            }
        }
        while (g_gen == mygen) { }
        __threadfence();
    }
    __syncthreads();
    mygen++;
}

// ---------------- persistent bidirectional LSTM layer ----------------
// 148 blocks; dir = bid&1 (74 blocks per direction), unit u = (bid>>1)*11 + warp.
// h_prev staged per step via ONE cp.async.bulk (100KB) into smem; weights stay
// L1-resident (no big LDG staging, ~125KB L1D left); cell state c in registers.
template <int LAYER>
__global__ void __launch_bounds__(NTHR, 1) k_layer(const float* __restrict__ WhhF,
                                                   const float* __restrict__ WhhB)
{
    extern __shared__ float sH[];   // HH*BB floats + mbarrier at offset HH*BB
    const int warp = threadIdx.x >> 5;
    const int lane = threadIdx.x & 31;
    const int dir  = blockIdx.x & 1;
    const int u    = (blockIdx.x >> 1) * NW + warp;   // 0..813
    const bool active = (u < HH);

    float* hbuf = (LAYER == 0) ? d_h0T : d_h1T;
    const float* Whh = dir ? WhhB : WhhF;
    const int uu = active ? u : 0;
    const float* w0 = Whh + (size_t)uu * HH;
    const float* w1 = Whh + (size_t)(uu + HH) * HH;
    const float* w2 = Whh + (size_t)(uu + 2 * HH) * HH;
    const float* w3 = Whh + (size_t)(uu + 3 * HH) * HH;

    uint32_t sbase = smem_u32(sH);
    uint32_t mbar = sbase + HH * BB * 4;
    if (threadIdx.x == 0) mbar_init(mbar, 1);
    __syncthreads();

    unsigned mygen = g_gen;
    uint32_t phase = 0;
    float c = 0.f;

    for (int s = 0; s < TT; s++) {
        const int t = dir ? (TT - 1 - s) : s;
        if (s > 0) {
            gsync(mygen);
            const int tp = dir ? (t + 1) : (t - 1);
            const float* src = hbuf + (size_t)tp * (K1 * BB) + (size_t)dir * HH * BB;
            if (threadIdx.x == 0) {
                mbar_expect_tx(mbar, HH * BB * 4);
                bulk_g2s(sbase, src, HH * BB * 4, mbar);
            }
            mbar_wait(mbar, phase);
            phase ^= 1;
        }

        if (active) {
            // hoist xg loads (DRAM) so they land while the dot product runs
            const float* xg = d_xg + (size_t)(dir * TT + t) * 3200 * BB;
            float x0 = __ldg(xg + (size_t)(uu         ) * BB + lane);
            float x1 = __ldg(xg + (size_t)(uu +     HH) * BB + lane);
            float x2 = __ldg(xg + (size_t)(uu + 2 * HH) * BB + lane);
            float x3 = __ldg(xg + (size_t)(uu + 3 * HH) * BB + lane);

            float d0 = 0.f, d1 = 0.f, d2 = 0.f, d3 = 0.f;
            if (s > 0) {
                #pragma unroll 2
                for (int k = 0; k < HH; k += 4) {
                    float4 W0 = *(const float4*)(w0 + k);
                    float4 W1 = *(const float4*)(w1 + k);
                    float4 W2 = *(const float4*)(w2 + k);
                    float4 W3 = *(const float4*)(w3 + k);
                    float v0 = sH[(k + 0) * BB + lane];
                    float v1 = sH[(k + 1) * BB + lane];
                    float v2 = sH[(k + 2) * BB + lane];
                    float v3 = sH[(k + 3) * BB + lane];
                    d0 = fmaf(W0.x, v0, d0); d0 = fmaf(W0.y, v1, d0); d0 = fmaf(W0.z, v2, d0); d0 = fmaf(W0.w, v3, d0);
                    d1 = fmaf(W1.x, v0, d1); d1 = fmaf(W1.y, v1, d1); d1 = fmaf(W1.z, v2, d1); d1 = fmaf(W1.w, v3, d1);
                    d2 = fmaf(W2.x, v0, d2); d2 = fmaf(W2.y, v1, d2); d2 = fmaf(W2.z, v2, d2); d2 = fmaf(W2.w, v3, d2);
                    d3 = fmaf(W3.x, v0, d3); d3 = fmaf(W3.y, v1, d3); d3 = fmaf(W3.z, v2, d3); d3 = fmaf(W3.w, v3, d3);
                }
            }
            float a0 = x0 + d0;
            float a1 = x1 + d1;
            float a2 = x2 + d2;
            float a3 = x3 + d3;

            float ig = 1.f / (1.f + expf(-a0));
            float fg = 1.f / (1.f + expf(-a1));
            float gg = tanhf(a2);
            float og = 1.f / (1.f + expf(-a3));
            c = (s == 0) ? (ig * gg) : (fg * c + ig * gg);
            float h = og * tanhf(c);

            hbuf[(size_t)t * (K1 * BB) + (size_t)(dir * HH + uu) * BB + lane] = h;
        }
    }
}

// ---------------- fc + softmax + dihedral ----------------
#define RNN_OUT 1653
#define AA 60
__global__ void k_fc(const float* __restrict__ fcW, const float* __restrict__ fcb,
                     const float* __restrict__ alphabet)
{
    const int t = blockIdx.x;
    __shared__ float sbuf[256 * BB];
    __shared__ float slog[AA * 33];
    const int tid  = threadIdx.x;
    const int warp = tid >> 5;
    const int lane = tid & 31;

    float acc[8];
    #pragma unroll
    for (int j = 0; j < 8; j++) {
        int a = warp * 8 + j;
        acc[j] = (a < AA) ? fcb[a] : 0.f;
    }

    for (int chunk = 0; chunk < RNN_OUT; chunk += 256) {
        int nk = min(256, RNN_OUT - chunk);
        for (int i = tid; i < nk * BB; i += blockDim.x) {
            int r = chunk + (i >> 5);
            int b = i & 31;
            float v = (r < K1)
                ? d_h1T[(size_t)t * K1 * BB + (size_t)r * BB + b]
                : d_xT[(size_t)t * 64 * BB + (size_t)(r - K1) * BB + b];
            sbuf[i] = v;
        }
        __syncthreads();
        #pragma unroll
        for (int j = 0; j < 8; j++) {
            int a = warp * 8 + j;
            if (a < AA) {
                const float* wr = fcW + (size_t)a * RNN_OUT + chunk;
                float aj = acc[j];
                for (int k = 0; k < nk; k++)
                    aj = fmaf(__ldg(wr + k), sbuf[k * BB + lane], aj);
                acc[j] = aj;
            }
        }
        __syncthreads();
    }

    #pragma unroll
    for (int j = 0; j < 8; j++) {
        int a = warp * 8 + j;
        if (a < AA) slog[a * 33 + lane] = acc[j];
    }
    __syncthreads();

    if (tid < BB) {
        int b = tid;
        float mx = -1e30f;
        for (int a = 0; a < AA; a++) mx = fmaxf(mx, slog[a * 33 + b]);
        float sum = 0.f;
        for (int a = 0; a < AA; a++) {
            float e = expf(slog[a * 33 + b] - mx);
            slog[a * 33 + b] = e;
            sum += e;
        }
        float inv = 1.f / sum;
        float ss0 = 0, ss1 = 0, ss2 = 0, cc0 = 0, cc1 = 0, cc2 = 0;
        for (int a = 0; a < AA; a++) {
            float p = slog[a * 33 + b] * inv;
            float l0 = alphabet[a * 3 + 0], l1 = alphabet[a * 3 + 1], l2 = alphabet[a * 3 + 2];
            ss0 = fmaf(p, sinf(l0), ss0); cc0 = fmaf(p, cosf(l0), cc0);
            ss1 = fmaf(p, sinf(l1), ss1); cc1 = fmaf(p, cosf(l1), cc1);
            ss2 = fmaf(p, sinf(l2), ss2); cc2 = fmaf(p, cosf(l2), cc2);
        }
        d_dih[(t * BB + b) * 3 + 0] = atan2f(ss0, cc0);
        d_dih[(t * BB + b) * 3 + 1] = atan2f(ss1, cc1);
        d_dih[(t * BB + b) * 3 + 2] = atan2f(ss2, cc2);
    }
}

// ---------------- NeRF chain (sequential, one thread per batch) ----------------
struct V3 { float x, y, z; };
__device__ __forceinline__ V3 v3sub(V3 a, V3 b) { return {a.x - b.x, a.y - b.y, a.z - b.z}; }
__device__ __forceinline__ V3 v3cross(V3 a, V3 b) {
    return {a.y * b.z - a.z * b.y, a.z * b.x - a.x * b.z, a.x * b.y - a.y * b.x};
}
__device__ __forceinline__ V3 v3norm(V3 a) {
    float inv = 1.f / sqrtf(a.x * a.x + a.y * a.y + a.z * a.z + 1e-12f);
    return {a.x * inv, a.y * inv, a.z * inv};
}

__global__ void k_nerf(float* __restrict__ out)
{
    int b = threadIdx.x;
    if (b >= BB) return;

    V3 A  = {-0.70710678118654752f, 1.22474487139158905f, 0.f};
    V3 Bv = {-1.41421356237309505f, 0.f, 0.f};
    V3 C  = {0.f, 0.f, 0.f};

    const float bl[3] = {145.801f, 152.326f, 132.868f};
    const float ba[3] = {2.124f, 1.941f, 2.028f};
    float rct[3], rst[3];
    #pragma unroll
    for (int j = 0; j < 3; j++) {
        float th = 3.14159265358979323846f - ba[j];
        rct[j] = bl[j] * cosf(th);
        rst[j] = bl[j] * sinf(th);
    }

    for (int t = 0; t < TT; t++) {
        #pragma unroll
        for (int j = 0; j < 3; j++) {
            float phi = d_dih[(t * BB + b) * 3 + j];
            V3 p = {rct[j], cosf(phi) * rst[j], sinf(phi) * rst[j]};
            V3 bc = v3norm(v3sub(C, Bv));
            V3 n  = v3norm(v3cross(v3sub(Bv, A), bc));
            V3 nxbc = v3cross(n, bc);
            V3 coord = {
                C.x + p.x * bc.x + p.y * nxbc.x + p.z * n.x,
                C.y + p.x * bc.y + p.y * nxbc.y + p.z * n.y,
                C.z + p.x * bc.z + p.y * nxbc.z + p.z * n.z
            };
            size_t o = ((size_t)(3 * t + j) * BB + b) * 3;
            out[o + 0] = coord.x;
            out[o + 1] = coord.y;
            out[o + 2] = coord.z;
            A = Bv; Bv = C; C = coord;
        }
    }
}

// ---------------- launch ----------------
extern "C" void kernel_launch(void* const* d_in, const int* in_sizes, int n_in,
                              void* d_out, int out_size)
{
    int base = 2;
    if (base < n_in && in_sizes[base] == 1) base = 3;

    const int*   primary = (const int*)  d_in[0];
    const float* evo     = (const float*)d_in[1];
    const float* emb     = (const float*)d_in[base + 0];
    const float* Wih0f   = (const float*)d_in[base + 1];
    const float* Whh0f   = (const float*)d_in[base + 2];
    const float* b0f     = (const float*)d_in[base + 3];
    const float* Wih0b   = (const float*)d_in[base + 4];
    const float* Whh0b   = (const float*)d_in[base + 5];
    const float* b0b     = (const float*)d_in[base + 6];
    const float* Wih1f   = (const float*)d_in[base + 7];
    const float* Whh1f   = (const float*)d_in[base + 8];
    const float* b1f     = (const float*)d_in[base + 9];
    const float* Wih1b   = (const float*)d_in[base + 10];
    const float* Whh1b   = (const float*)d_in[base + 11];
    const float* b1b     = (const float*)d_in[base + 12];
    const float* fcW     = (const float*)d_in[base + 13];
    const float* fcb     = (const float*)d_in[base + 14];
    const float* alphabet= (const float*)d_in[base + 15];

    const int SMEM_SEG = HH * BB * sizeof(float) + 64;     // 102464 (h tile + mbarrier)
    const int SMEM_XG1 = K1 * BB * sizeof(float);          // 204800
    cudaFuncSetAttribute(k_layer<0>, cudaFuncAttributeMaxDynamicSharedMemorySize, SMEM_SEG);
    cudaFuncSetAttribute(k_layer<1>, cudaFuncAttributeMaxDynamicSharedMemorySize, SMEM_SEG);
    cudaFuncSetAttribute((const void*)k_xg<K1, K1, 1>, cudaFuncAttributeMaxDynamicSharedMemorySize, SMEM_XG1);

    k_prep<<<(TT * 64 * BB + 255) / 256, 256>>>(primary, evo, emb);
    k_trans<<<512, 256>>>(Wih0f, Wih0b, Wih1f, Wih1b);

    dim3 gxg(TT, 2, 1);
    k_xg<DINX, 64, 0><<<gxg, 256, DINX * BB * sizeof(float)>>>(b0f, b0b);
    k_layer<0><<<GRID, NTHR, SMEM_SEG>>>(Whh0f, Whh0b);
    k_xg<K1, K1, 1><<<gxg, 256, SMEM_XG1>>>(b1f, b1b);
    k_layer<1><<<GRID, NTHR, SMEM_SEG>>>(Whh1f, Whh1b);

    k_fc<<<TT, 256>>>(fcW, fcb, alphabet);
    k_nerf<<<1, 32>>>((float*)d_out);
}

// round 8
// speedup vs baseline: 1.0008x; 1.0008x over previous
#include <cuda_runtime.h>
#include <math.h>
#include <stdint.h>

#define TT 700
#define BB 32
#define HH 800
#define K1 1600
#define DINX 53
#define GRID 148
#define NW 11
#define NTHR (NW * 32)

// ---------------- scratch (static device globals; no allocation) ----------------
__device__ float d_xT [TT * 64 * BB];         // [t][k(64 padded)][b]
__device__ float d_h0T[TT * K1 * BB];         // [t][row 0..1599][b]  f=[0,800) b=[800,1600)
__device__ float d_h1T[TT * K1 * BB];
__device__ float d_xg [2 * TT * 3200 * BB];   // [dir][t][gate-row 0..3199][b]  (bias folded)
__device__ float d_Wt0f[DINX * 3200];         // transposed Wih0: [k][row]
__device__ float d_Wt0b[DINX * 3200];
__device__ float d_Wt1f[K1 * 3200];
__device__ float d_Wt1b[K1 * 3200];
__device__ float d_dih[TT * BB * 3];

// global barrier state (zero-initialized)
__device__ unsigned g_cnt[8];
__device__ unsigned g_master;
__device__ volatile unsigned g_gen;

// ---------------- small PTX helpers ----------------
__device__ __forceinline__ uint32_t smem_u32(const void* p) {
    uint32_t a;
    asm("{ .reg .u64 t; cvta.to.shared.u64 t, %1; cvt.u32.u64 %0, t; }" : "=r"(a) : "l"(p));
    return a;
}
__device__ __forceinline__ void mbar_init(uint32_t mbar, uint32_t count) {
    asm volatile("mbarrier.init.shared.b64 [%0], %1;" :: "r"(mbar), "r"(count) : "memory");
}
__device__ __forceinline__ void mbar_expect_tx(uint32_t mbar, uint32_t bytes) {
    asm volatile("mbarrier.arrive.expect_tx.shared.b64 _, [%0], %1;" :: "r"(mbar), "r"(bytes) : "memory");
}
__device__ __forceinline__ void bulk_g2s(uint32_t dst, const void* src, uint32_t bytes, uint32_t mbar) {
    asm volatile("cp.async.bulk.shared::cluster.global.mbarrier::complete_tx::bytes [%0], [%1], %2, [%3];"
                 :: "r"(dst), "l"(src), "r"(bytes), "r"(mbar) : "memory");
}
__device__ __forceinline__ void mbar_wait(uint32_t mbar, uint32_t phase) {
    asm volatile(
        "{\n\t.reg .pred P1;\n\t"
        "W%=:\n\t"
        "mbarrier.try_wait.parity.acquire.cta.shared::cta.b64 P1, [%0], %1, 0x989680;\n\t"
        "@P1 bra D%=;\n\t"
        "bra W%=;\n\t"
        "D%=:\n\t}"
        :: "r"(mbar), "r"(phase) : "memory");
}

// ---------------- prep: x = concat(emb[primary], evolutionary), transposed ----------------
__global__ void k_prep(const int* __restrict__ primary,
                       const float* __restrict__ evo,
                       const float* __restrict__ emb)
{
    int idx = blockIdx.x * blockDim.x + threadIdx.x;
    if (idx >= TT * 64 * BB) return;
    int b = idx & 31;
    int k = (idx >> 5) & 63;
    int t = idx >> 11;
    float v = 0.f;
    if (k < 32) {
        int aa = primary[t * BB + b];
        v = emb[aa * 32 + k];
    } else if (k < DINX) {
        v = evo[(t * BB + b) * 21 + (k - 32)];
    }
    d_xT[idx] = v;
}

// ---------------- transpose input weights into [k][row] ----------------
__global__ void k_trans(const float* __restrict__ W0f, const float* __restrict__ W0b,
                        const float* __restrict__ W1f, const float* __restrict__ W1b)
{
    const int N0 = 3200 * DINX;
    const int N1 = 3200 * K1;
    const int NT = 2 * N0 + 2 * N1;
    for (int i = blockIdx.x * blockDim.x + threadIdx.x; i < NT; i += gridDim.x * blockDim.x) {
        if (i < N0) {
            int r = i / DINX, k = i % DINX;
            d_Wt0f[k * 3200 + r] = W0f[i];
        } else if (i < 2 * N0) {
            int j = i - N0;
            int r = j / DINX, k = j % DINX;
            d_Wt0b[k * 3200 + r] = W0b[j];
        } else if (i < 2 * N0 + N1) {
            int j = i - 2 * N0;
            int r = j / K1, k = j % K1;
            d_Wt1f[(size_t)k * 3200 + r] = W1f[j];
        } else {
            int j = i - 2 * N0 - N1;
            int r = j / K1, k = j % K1;
            d_Wt1b[(size_t)k * 3200 + r] = W1b[j];
        }
    }
}

// ---------------- xg precompute: xg[dir][t][r][b] = bias[r] + sum_k Wt[k][r] * src[t][k][b] ----------------
template <int KK, int SSTR, int LAYER>
__global__ void k_xg(const float* __restrict__ bF, const float* __restrict__ bB)
{
    extern __shared__ float sx[];   // KK * 32 floats
    const int t = blockIdx.x;
    const int dir = blockIdx.y;
    const float* Wt   = (LAYER == 0) ? (dir ? d_Wt0b : d_Wt0f) : (dir ? d_Wt1b : d_Wt1f);
    const float* bias = dir ? bB : bF;
    const float* src  = (LAYER == 0) ? d_xT : d_h0T;
    const float* s0 = src + (size_t)t * SSTR * BB;

    for (int i = threadIdx.x; i < KK * BB / 4; i += blockDim.x)
        ((float4*)sx)[i] = ((const float4*)s0)[i];
    __syncthreads();

    float* out = d_xg + (size_t)(dir * TT + t) * 3200 * BB;
    for (int r = threadIdx.x; r < 3200; r += blockDim.x) {
        float acc[32];
        #pragma unroll
        for (int j = 0; j < 32; j++) acc[j] = 0.f;
        const float* wp = Wt + r;
        for (int k = 0; k < KK; k++) {
            float w = wp[(size_t)k * 3200];
            const float4* xv = (const float4*)(sx + k * 32);
            #pragma unroll
            for (int j = 0; j < 8; j++) {
                float4 v = xv[j];
                acc[4 * j + 0] = fmaf(w, v.x, acc[4 * j + 0]);
                acc[4 * j + 1] = fmaf(w, v.y, acc[4 * j + 1]);
                acc[4 * j + 2] = fmaf(w, v.z, acc[4 * j + 2]);
                acc[4 * j + 3] = fmaf(w, v.w, acc[4 * j + 3]);
            }
        }
        float bv = bias[r];
        float4* op = (float4*)(out + (size_t)r * BB);
        #pragma unroll
        for (int j = 0; j < 8; j++) {
            float4 v4;
            v4.x = acc[4 * j + 0] + bv;
            v4.y = acc[4 * j + 1] + bv;
            v4.z = acc[4 * j + 2] + bv;
            v4.w = acc[4 * j + 3] + bv;
            op[j] = v4;
        }
    }
}

// ---------------- hierarchical grid-wide barrier ----------------
__device__ __forceinline__ void gsync(unsigned& mygen)
{
    __syncthreads();
    if (threadIdx.x == 0) {
        __threadfence();
        int grp = blockIdx.x & 7;
        unsigned sz = (grp < 4) ? 19u : 18u;   // 148 = 4*19 + 4*18
        unsigned v = atomicAdd(&g_cnt[grp], 1u);
        if (v == sz - 1u) {
            g_cnt[grp] = 0u;
            __threadfence();
            unsigned m = atomicAdd(&g_master, 1u);
            if (m == 7u) {
                g_master = 0u;
                __threadfence();
                g_gen = mygen + 1u;
            }
        }
        while (g_gen == mygen) { }
        __threadfence();
    }
    __syncthreads();
    mygen++;
}

// ---------------- persistent bidirectional LSTM layer ----------------
// 148 blocks; dir = bid&1 (74 blocks per direction), unit u = (bid>>1)*11 + warp.
// h_prev staged per step via ONE cp.async.bulk (100KB) into smem; weights stay
// L1-resident (no big LDG staging, ~125KB L1D left); cell state c in registers.
template <int LAYER>
__global__ void __launch_bounds__(NTHR, 1) k_layer(const float* __restrict__ WhhF,
                                                   const float* __restrict__ WhhB)
{
    extern __shared__ float sH[];   // HH*BB floats + mbarrier at offset HH*BB
    const int warp = threadIdx.x >> 5;
    const int lane = threadIdx.x & 31;
    const int dir  = blockIdx.x & 1;
    const int u    = (blockIdx.x >> 1) * NW + warp;   // 0..813
    const bool active = (u < HH);

    float* hbuf = (LAYER == 0) ? d_h0T : d_h1T;
    const float* Whh = dir ? WhhB : WhhF;
    const int uu = active ? u : 0;
    const float* w0 = Whh + (size_t)uu * HH;
    const float* w1 = Whh + (size_t)(uu + HH) * HH;
    const float* w2 = Whh + (size_t)(uu + 2 * HH) * HH;
    const float* w3 = Whh + (size_t)(uu + 3 * HH) * HH;

    uint32_t sbase = smem_u32(sH);
    uint32_t mbar = sbase + HH * BB * 4;
    if (threadIdx.x == 0) mbar_init(mbar, 1);
    __syncthreads();

    unsigned mygen = g_gen;
    uint32_t phase = 0;
    float c = 0.f;

    for (int s = 0; s < TT; s++) {
        const int t = dir ? (TT - 1 - s) : s;
        if (s > 0) {
            gsync(mygen);
            const int tp = dir ? (t + 1) : (t - 1);
            const float* src = hbuf + (size_t)tp * (K1 * BB) + (size_t)dir * HH * BB;
            if (threadIdx.x == 0) {
                mbar_expect_tx(mbar, HH * BB * 4);
                bulk_g2s(sbase, src, HH * BB * 4, mbar);
            }
            mbar_wait(mbar, phase);
            phase ^= 1;
        }

        if (active) {
            // hoist xg loads (DRAM) so they land while the dot product runs
            const float* xg = d_xg + (size_t)(dir * TT + t) * 3200 * BB;
            float x0 = __ldg(xg + (size_t)(uu         ) * BB + lane);
            float x1 = __ldg(xg + (size_t)(uu +     HH) * BB + lane);
            float x2 = __ldg(xg + (size_t)(uu + 2 * HH) * BB + lane);
            float x3 = __ldg(xg + (size_t)(uu + 3 * HH) * BB + lane);

            float d0 = 0.f, d1 = 0.f, d2 = 0.f, d3 = 0.f;
            if (s > 0) {
                #pragma unroll 2
                for (int k = 0; k < HH; k += 4) {
                    float4 W0 = *(const float4*)(w0 + k);
                    float4 W1 = *(const float4*)(w1 + k);
                    float4 W2 = *(const float4*)(w2 + k);
                    float4 W3 = *(const float4*)(w3 + k);
                    float v0 = sH[(k + 0) * BB + lane];
                    float v1 = sH[(k + 1) * BB + lane];
                    float v2 = sH[(k + 2) * BB + lane];
                    float v3 = sH[(k + 3) * BB + lane];
                    d0 = fmaf(W0.x, v0, d0); d0 = fmaf(W0.y, v1, d0); d0 = fmaf(W0.z, v2, d0); d0 = fmaf(W0.w, v3, d0);
                    d1 = fmaf(W1.x, v0, d1); d1 = fmaf(W1.y, v1, d1); d1 = fmaf(W1.z, v2, d1); d1 = fmaf(W1.w, v3, d1);
                    d2 = fmaf(W2.x, v0, d2); d2 = fmaf(W2.y, v1, d2); d2 = fmaf(W2.z, v2, d2); d2 = fmaf(W2.w, v3, d2);
                    d3 = fmaf(W3.x, v0, d3); d3 = fmaf(W3.y, v1, d3); d3 = fmaf(W3.z, v2, d3); d3 = fmaf(W3.w, v3, d3);
                }
            }
            float a0 = x0 + d0;
            float a1 = x1 + d1;
            float a2 = x2 + d2;
            float a3 = x3 + d3;

            float ig = 1.f / (1.f + expf(-a0));
            float fg = 1.f / (1.f + expf(-a1));
            float gg = tanhf(a2);
            float og = 1.f / (1.f + expf(-a3));
            c = (s == 0) ? (ig * gg) : (fg * c + ig * gg);
            float h = og * tanhf(c);

            hbuf[(size_t)t * (K1 * BB) + (size_t)(dir * HH + uu) * BB + lane] = h;
        }
    }
}

// ---------------- fc + softmax + dihedral ----------------
#define RNN_OUT 1653
#define AA 60
__global__ void k_fc(const float* __restrict__ fcW, const float* __restrict__ fcb,
                     const float* __restrict__ alphabet)
{
    const int t = blockIdx.x;
    __shared__ float sbuf[256 * BB];
    __shared__ float slog[AA * 33];
    const int tid  = threadIdx.x;
    const int warp = tid >> 5;
    const int lane = tid & 31;

    float acc[8];
    #pragma unroll
    for (int j = 0; j < 8; j++) {
        int a = warp * 8 + j;
        acc[j] = (a < AA) ? fcb[a] : 0.f;
    }

    for (int chunk = 0; chunk < RNN_OUT; chunk += 256) {
        int nk = min(256, RNN_OUT - chunk);
        for (int i = tid; i < nk * BB; i += blockDim.x) {
            int r = chunk + (i >> 5);
            int b = i & 31;
            float v = (r < K1)
                ? d_h1T[(size_t)t * K1 * BB + (size_t)r * BB + b]
                : d_xT[(size_t)t * 64 * BB + (size_t)(r - K1) * BB + b];
            sbuf[i] = v;
        }
        __syncthreads();
        #pragma unroll
        for (int j = 0; j < 8; j++) {
            int a = warp * 8 + j;
            if (a < AA) {
                const float* wr = fcW + (size_t)a * RNN_OUT + chunk;
                float aj = acc[j];
                for (int k = 0; k < nk; k++)
                    aj = fmaf(__ldg(wr + k), sbuf[k * BB + lane], aj);
                acc[j] = aj;
            }
        }
        __syncthreads();
    }

    #pragma unroll
    for (int j = 0; j < 8; j++) {
        int a = warp * 8 + j;
        if (a < AA) slog[a * 33 + lane] = acc[j];
    }
    __syncthreads();

    if (tid < BB) {
        int b = tid;
        float mx = -1e30f;
        for (int a = 0; a < AA; a++) mx = fmaxf(mx, slog[a * 33 + b]);
        float sum = 0.f;
        for (int a = 0; a < AA; a++) {
            float e = expf(slog[a * 33 + b] - mx);
            slog[a * 33 + b] = e;
            sum += e;
        }
        float inv = 1.f / sum;
        float ss0 = 0, ss1 = 0, ss2 = 0, cc0 = 0, cc1 = 0, cc2 = 0;
        for (int a = 0; a < AA; a++) {
            float p = slog[a * 33 + b] * inv;
            float l0 = alphabet[a * 3 + 0], l1 = alphabet[a * 3 + 1], l2 = alphabet[a * 3 + 2];
            ss0 = fmaf(p, sinf(l0), ss0); cc0 = fmaf(p, cosf(l0), cc0);
            ss1 = fmaf(p, sinf(l1), ss1); cc1 = fmaf(p, cosf(l1), cc1);
            ss2 = fmaf(p, sinf(l2), ss2); cc2 = fmaf(p, cosf(l2), cc2);
        }
        d_dih[(t * BB + b) * 3 + 0] = atan2f(ss0, cc0);
        d_dih[(t * BB + b) * 3 + 1] = atan2f(ss1, cc1);
        d_dih[(t * BB + b) * 3 + 2] = atan2f(ss2, cc2);
    }
}

// ---------------- NeRF chain (sequential, one thread per batch) ----------------
struct V3 { float x, y, z; };
__device__ __forceinline__ V3 v3sub(V3 a, V3 b) { return {a.x - b.x, a.y - b.y, a.z - b.z}; }
__device__ __forceinline__ V3 v3cross(V3 a, V3 b) {
    return {a.y * b.z - a.z * b.y, a.z * b.x - a.x * b.z, a.x * b.y - a.y * b.x};
}
__device__ __forceinline__ V3 v3norm(V3 a) {
    float inv = 1.f / sqrtf(a.x * a.x + a.y * a.y + a.z * a.z + 1e-12f);
    return {a.x * inv, a.y * inv, a.z * inv};
}

__global__ void k_nerf(float* __restrict__ out)
{
    int b = threadIdx.x;
    if (b >= BB) return;

    V3 A  = {-0.70710678118654752f, 1.22474487139158905f, 0.f};
    V3 Bv = {-1.41421356237309505f, 0.f, 0.f};
    V3 C  = {0.f, 0.f, 0.f};

    const float bl[3] = {145.801f, 152.326f, 132.868f};
    const float ba[3] = {2.124f, 1.941f, 2.028f};
    float rct[3], rst[3];
    #pragma unroll
    for (int j = 0; j < 3; j++) {
        float th = 3.14159265358979323846f - ba[j];
        rct[j] = bl[j] * cosf(th);
        rst[j] = bl[j] * sinf(th);
    }

    for (int t = 0; t < TT; t++) {
        #pragma unroll
        for (int j = 0; j < 3; j++) {
            float phi = d_dih[(t * BB + b) * 3 + j];
            V3 p = {rct[j], cosf(phi) * rst[j], sinf(phi) * rst[j]};
            V3 bc = v3norm(v3sub(C, Bv));
            V3 n  = v3norm(v3cross(v3sub(Bv, A), bc));
            V3 nxbc = v3cross(n, bc);
            V3 coord = {
                C.x + p.x * bc.x + p.y * nxbc.x + p.z * n.x,
                C.y + p.x * bc.y + p.y * nxbc.y + p.z * n.y,
                C.z + p.x * bc.z + p.y * nxbc.z + p.z * n.z
            };
            size_t o = ((size_t)(3 * t + j) * BB + b) * 3;
            out[o + 0] = coord.x;
            out[o + 1] = coord.y;
            out[o + 2] = coord.z;
            A = Bv; Bv = C; C = coord;
        }
    }
}

// ---------------- launch ----------------
extern "C" void kernel_launch(void* const* d_in, const int* in_sizes, int n_in,
                              void* d_out, int out_size)
{
    int base = 2;
    if (base < n_in && in_sizes[base] == 1) base = 3;

    const int*   primary = (const int*)  d_in[0];
    const float* evo     = (const float*)d_in[1];
    const float* emb     = (const float*)d_in[base + 0];
    const float* Wih0f   = (const float*)d_in[base + 1];
    const float* Whh0f   = (const float*)d_in[base + 2];
    const float* b0f     = (const float*)d_in[base + 3];
    const float* Wih0b   = (const float*)d_in[base + 4];
    const float* Whh0b   = (const float*)d_in[base + 5];
    const float* b0b     = (const float*)d_in[base + 6];
    const float* Wih1f   = (const float*)d_in[base + 7];
    const float* Whh1f   = (const float*)d_in[base + 8];
    const float* b1f     = (const float*)d_in[base + 9];
    const float* Wih1b   = (const float*)d_in[base + 10];
    const float* Whh1b   = (const float*)d_in[base + 11];
    const float* b1b     = (const float*)d_in[base + 12];
    const float* fcW     = (const float*)d_in[base + 13];
    const float* fcb     = (const float*)d_in[base + 14];
    const float* alphabet= (const float*)d_in[base + 15];

    const int SMEM_SEG = HH * BB * sizeof(float) + 64;     // 102464 (h tile + mbarrier)
    const int SMEM_XG1 = K1 * BB * sizeof(float);          // 204800
    cudaFuncSetAttribute(k_layer<0>, cudaFuncAttributeMaxDynamicSharedMemorySize, SMEM_SEG);
    cudaFuncSetAttribute(k_layer<1>, cudaFuncAttributeMaxDynamicSharedMemorySize, SMEM_SEG);
    cudaFuncSetAttribute((const void*)k_xg<K1, K1, 1>, cudaFuncAttributeMaxDynamicSharedMemorySize, SMEM_XG1);

    k_prep<<<(TT * 64 * BB + 255) / 256, 256>>>(primary, evo, emb);
    k_trans<<<512, 256>>>(Wih0f, Wih0b, Wih1f, Wih1b);

    dim3 gxg(TT, 2, 1);
    k_xg<DINX, 64, 0><<<gxg, 256, DINX * BB * sizeof(float)>>>(b0f, b0b);
    k_layer<0><<<GRID, NTHR, SMEM_SEG>>>(Whh0f, Whh0b);
    k_xg<K1, K1, 1><<<gxg, 256, SMEM_XG1>>>(b1f, b1b);
    k_layer<1><<<GRID, NTHR, SMEM_SEG>>>(Whh1f, Whh1b);

    k_fc<<<TT, 256>>>(fcW, fcb, alphabet);
    k_nerf<<<1, 32>>>((float*)d_out);
}

// round 11
// speedup vs baseline: 1.2265x; 1.2255x over previous
#include <cuda_runtime.h>
#include <cuda_bf16.h>
#include <math.h>
#include <stdint.h>

#define TT 700
#define BB 32
#define HH 800
#define K1 1600
#define DINX 53
#define AA 60
#define RNN_OUT 1653
#define RGRID 100

// ---------------- static device buffers ----------------
__device__ float d_xT [TT * 64 * BB];
__device__ float d_h0T[(size_t)TT * K1 * BB];
__device__ float d_h1T[(size_t)TT * K1 * BB];
__device__ float d_xg [(size_t)2 * TT * 3200 * BB];
__device__ float d_Wt0f[DINX * 3200];
__device__ float d_Wt0b[DINX * 3200];
__device__ float d_Wt1f[(size_t)K1 * 3200];
__device__ float d_Wt1b[(size_t)K1 * 3200];
__device__ float d_dih[TT * BB * 3];
// A in MMA-fragment-packed bf16 hi/lo: [layer][dir][wt 0..199][kc 0..49][lane][q 0..7]
// q = 0..3 hi regs a0..a3, 4..7 lo regs  (each uint32 = 2 bf16)
__device__ __align__(16) uint32_t d_Apack[(size_t)2 * 2 * 200 * 50 * 32 * 8];
// B (=h) fragment-packed: [parity][dir][kc 0..49][nt 0..3][lane][4]: b0hi,b1hi,b0lo,b1lo
__device__ __align__(16) uint32_t d_Bpack[2][2][50 * 4 * 32 * 4];

// grid barrier (zero-init)
__device__ unsigned g_cnt[8];
__device__ unsigned g_master;
__device__ volatile unsigned g_gen;

// ---------------- mma.sync helper (base sm_80+ feature; compiles on compute_103) ----------------
__device__ __forceinline__ void mma16816(float& d0, float& d1, float& d2, float& d3,
                                         uint32_t a0, uint32_t a1, uint32_t a2, uint32_t a3,
                                         uint32_t b0, uint32_t b1)
{
    asm volatile("mma.sync.aligned.m16n8k16.row.col.f32.bf16.bf16.f32 "
                 "{%0,%1,%2,%3},{%4,%5,%6,%7},{%8,%9},{%0,%1,%2,%3};"
                 : "+f"(d0), "+f"(d1), "+f"(d2), "+f"(d3)
                 : "r"(a0), "r"(a1), "r"(a2), "r"(a3), "r"(b0), "r"(b1));
}

// ---------------- prep ----------------
__global__ void k_prep(const int* __restrict__ primary, const float* __restrict__ evo,
                       const float* __restrict__ emb)
{
    int idx = blockIdx.x * blockDim.x + threadIdx.x;
    if (idx >= TT * 64 * BB) return;
    int b = idx & 31, k = (idx >> 5) & 63, t = idx >> 11;
    float v = 0.f;
    if (k < 32) v = emb[primary[t * BB + b] * 32 + k];
    else if (k < DINX) v = evo[(t * BB + b) * 21 + (k - 32)];
    d_xT[idx] = v;
}

// ---------------- transpose input weights [row][k]->[k][row] ----------------
__global__ void k_trans(const float* __restrict__ W0f, const float* __restrict__ W0b,
                        const float* __restrict__ W1f, const float* __restrict__ W1b)
{
    const int N0 = 3200 * DINX;
    const int N1 = 3200 * K1;
    for (int i = blockIdx.x * blockDim.x + threadIdx.x; i < 2 * N0 + 2 * N1; i += gridDim.x * blockDim.x) {
        if (i < N0) { int r = i / DINX, k = i % DINX; d_Wt0f[k * 3200 + r] = W0f[i]; }
        else if (i < 2 * N0) { int j2 = i - N0; int r = j2 / DINX, k = j2 % DINX; d_Wt0b[k * 3200 + r] = W0b[j2]; }
        else if (i < 2 * N0 + N1) { int j2 = i - 2 * N0; int r = j2 / K1, k = j2 % K1; d_Wt1f[(size_t)k * 3200 + r] = W1f[j2]; }
        else { int j2 = i - 2 * N0 - N1; int r = j2 / K1, k = j2 % K1; d_Wt1b[(size_t)k * 3200 + r] = W1b[j2]; }
    }
}

// ---------------- pack recurrent weights into MMA A-fragment order ----------------
// permuted row p = u*4+g; warp-tile wt covers p in [wt*16, wt*16+16) = units wt*4..wt*4+3, all gates.
// m16n8k16 A frag: a0:(row=gid,  k=tg*2+{0,1})  a1:(row=gid+8, same k)
//                  a2:(row=gid,  k=tg*2+8+{0,1}) a3:(row=gid+8, k+8)
__global__ void k_wconv(const float* __restrict__ W0f, const float* __restrict__ W0b,
                        const float* __restrict__ W1f, const float* __restrict__ W1b)
{
    const size_t NTOT = (size_t)2 * 2 * 200 * 50 * 32 * 8;
    for (size_t i = (size_t)blockIdx.x * blockDim.x + threadIdx.x; i < NTOT;
         i += (size_t)gridDim.x * blockDim.x) {
        int q = (int)(i & 7);
        size_t r = i >> 3;
        int lane = (int)(r & 31); r >>= 5;
        int kc = (int)(r % 50); r /= 50;
        int wt = (int)(r % 200); r /= 200;
        int dir = (int)(r & 1);
        int layer = (int)(r >> 1);
        int ri = q & 3, pass = q >> 2;
        int gid = lane >> 2, tg = lane & 3;
        int p = wt * 16 + gid + (ri & 1) * 8;
        int u = p >> 2, g = p & 3;
        const float* W = layer ? (dir ? W1b : W1f) : (dir ? W0b : W0f);
        const float* wr = W + (size_t)(g * HH + u) * HH;
        uint32_t out = 0;
        #pragma unroll
        for (int hh = 0; hh < 2; hh++) {
            int k = kc * 16 + tg * 2 + hh + ((ri >> 1) & 1) * 8;
            float v = wr[k];
            __nv_bfloat16 hi = __float2bfloat16(v);
            __nv_bfloat16 bv = (pass == 0) ? hi : __float2bfloat16(v - __bfloat162float(hi));
            uint16_t bits = *(uint16_t*)&bv;
            out |= (uint32_t)bits << (hh * 16);
        }
        d_Apack[i] = out;
    }
}

// ---------------- xg precompute (FFMA; known-good) ----------------
template <int KK, int SSTR, int LAYER>
__global__ void k_xg(const float* __restrict__ bF, const float* __restrict__ bB)
{
    extern __shared__ float sx[];
    const int t = blockIdx.x;
    const int dir = blockIdx.y;
    const float* Wt   = (LAYER == 0) ? (dir ? d_Wt0b : d_Wt0f) : (dir ? d_Wt1b : d_Wt1f);
    const float* bias = dir ? bB : bF;
    const float* src  = (LAYER == 0) ? d_xT : d_h0T;
    const float* s0 = src + (size_t)t * SSTR * BB;

    for (int i = threadIdx.x; i < KK * BB / 4; i += blockDim.x)
        ((float4*)sx)[i] = ((const float4*)s0)[i];
    __syncthreads();

    float* out = d_xg + (size_t)(dir * TT + t) * 3200 * BB;
    for (int r = threadIdx.x; r < 3200; r += blockDim.x) {
        float acc[32];
        #pragma unroll
        for (int j = 0; j < 32; j++) acc[j] = 0.f;
        const float* wp = Wt + r;
        for (int k = 0; k < KK; k++) {
            float w = wp[(size_t)k * 3200];
            const float4* xv = (const float4*)(sx + k * 32);
            #pragma unroll
            for (int j = 0; j < 8; j++) {
                float4 v = xv[j];
                acc[4 * j + 0] = fmaf(w, v.x, acc[4 * j + 0]);
                acc[4 * j + 1] = fmaf(w, v.y, acc[4 * j + 1]);
                acc[4 * j + 2] = fmaf(w, v.z, acc[4 * j + 2]);
                acc[4 * j + 3] = fmaf(w, v.w, acc[4 * j + 3]);
            }
        }
        float bv = bias[r];
        float4* op = (float4*)(out + (size_t)r * BB);
        #pragma unroll
        for (int j = 0; j < 8; j++) {
            float4 v4 = {acc[4*j+0] + bv, acc[4*j+1] + bv, acc[4*j+2] + bv, acc[4*j+3] + bv};
            op[j] = v4;
        }
    }
}

// ---------------- hierarchical 100-CTA barrier ----------------
__device__ __forceinline__ void gsync100(unsigned& mygen)
{
    __syncthreads();
    if (threadIdx.x == 0) {
        __threadfence();
        int grp = blockIdx.x & 7;
        unsigned sz = (grp < 4) ? 13u : 12u;   // 100 = 4*13 + 4*12
        unsigned v = atomicAdd(&g_cnt[grp], 1u);
        if (v == sz - 1u) {
            g_cnt[grp] = 0u;
            __threadfence();
            unsigned m = atomicAdd(&g_master, 1u);
            if (m == 7u) {
                g_master = 0u;
                __threadfence();
                g_gen = mygen + 1u;
            }
        }
        while (g_gen == mygen) { }
        __threadfence();
    }
    __syncthreads();
    mygen++;
}

// ---------------- persistent mma.sync recurrent layer ----------------
// 100 CTAs: dir = bid&1, jt = bid>>1 (0..49) -> 64 permuted gate-rows = 16 units x 4 gates.
// 4 warps, warp w = row-tile wt = jt*4+w (16 rows). bf16x3, fp32 reg accumulators.
template <int LAYER>
__global__ void __launch_bounds__(128, 1) k_rec()
{
    __shared__ float sG[64 * 33];
    const int tid = threadIdx.x;
    const int w = tid >> 5, lane = tid & 31;
    const int dir = blockIdx.x & 1;
    const int jt = blockIdx.x >> 1;
    const int wt = jt * 4 + w;
    const int gid = lane >> 2, tg = lane & 3;

    float* hT = LAYER ? d_h1T : d_h0T;
    const uint4* Abase = (const uint4*)d_Apack + ((size_t)((LAYER * 2 + dir) * 200 + wt)) * 50 * 32 * 2;

    // epilogue mapping: thread -> (unit ul, batches b0..b0+3)
    const int ul = tid >> 3;
    const int b0 = (tid & 7) * 4;
    const int u = jt * 16 + ul;
    const int kc2 = u >> 4, kl = u & 15;
    const int ri2 = kl >> 3, rem = kl & 7, tg2 = rem >> 1, hh2 = rem & 1;

    unsigned mygen = g_gen;
    float cs[4] = {0.f, 0.f, 0.f, 0.f};

    for (int s = 0; s < TT; s++) {
        const int t = dir ? (TT - 1 - s) : s;
        if (s > 0) {
            gsync100(mygen);
            const uint4* Bb = (const uint4*)d_Bpack[s & 1][dir];
            float C[4][4];
            #pragma unroll
            for (int nt = 0; nt < 4; nt++)
                #pragma unroll
                for (int i = 0; i < 4; i++) C[nt][i] = 0.f;

            #pragma unroll 2
            for (int kc = 0; kc < 50; kc++) {
                uint4 ahi = Abase[(kc * 32 + lane) * 2];
                uint4 alo = Abase[(kc * 32 + lane) * 2 + 1];
                #pragma unroll
                for (int nt = 0; nt < 4; nt++) {
                    uint4 bf = Bb[(kc * 4 + nt) * 32 + lane];
                    mma16816(C[nt][0], C[nt][1], C[nt][2], C[nt][3],
                             ahi.x, ahi.y, ahi.z, ahi.w, bf.x, bf.y);   // hi*hi
                    mma16816(C[nt][0], C[nt][1], C[nt][2], C[nt][3],
                             alo.x, alo.y, alo.z, alo.w, bf.x, bf.y);   // lo*hi
                    mma16816(C[nt][0], C[nt][1], C[nt][2], C[nt][3],
                             ahi.x, ahi.y, ahi.z, ahi.w, bf.z, bf.w);   // hi*lo
                }
            }
            // C frag -> smem: c0:(row gid,col tg*2) c1:+1 c2:(row+8) c3:(row+8,+1)
            const int lr = w * 16 + gid;
            #pragma unroll
            for (int nt = 0; nt < 4; nt++) {
                int col = nt * 8 + tg * 2;
                sG[lr * 33 + col]           = C[nt][0];
                sG[lr * 33 + col + 1]       = C[nt][1];
                sG[(lr + 8) * 33 + col]     = C[nt][2];
                sG[(lr + 8) * 33 + col + 1] = C[nt][3];
            }
            __syncthreads();
        }

        // epilogue
        const float* xg = d_xg + (size_t)(dir * TT + t) * 3200 * BB;
        float4 xv0 = *(const float4*)(xg + (size_t)(0 * HH + u) * BB + b0);
        float4 xv1 = *(const float4*)(xg + (size_t)(1 * HH + u) * BB + b0);
        float4 xv2 = *(const float4*)(xg + (size_t)(2 * HH + u) * BB + b0);
        float4 xv3 = *(const float4*)(xg + (size_t)(3 * HH + u) * BB + b0);
        float hv[4];
        #pragma unroll
        for (int i = 0; i < 4; i++) {
            int b = b0 + i;
            float p0 = ((const float*)&xv0)[i];
            float p1 = ((const float*)&xv1)[i];
            float p2 = ((const float*)&xv2)[i];
            float p3 = ((const float*)&xv3)[i];
            if (s > 0) {
                p0 += sG[(ul * 4 + 0) * 33 + b];
                p1 += sG[(ul * 4 + 1) * 33 + b];
                p2 += sG[(ul * 4 + 2) * 33 + b];
                p3 += sG[(ul * 4 + 3) * 33 + b];
            }
            float ig = 1.f / (1.f + expf(-p0));
            float fg = 1.f / (1.f + expf(-p1));
            float gg = tanhf(p2);
            float og = 1.f / (1.f + expf(-p3));
            cs[i] = (s == 0) ? (ig * gg) : (fg * cs[i] + ig * gg);
            hv[i] = og * tanhf(cs[i]);
        }
        float4 hq = {hv[0], hv[1], hv[2], hv[3]};
        *(float4*)(hT + (size_t)t * (K1 * BB) + (size_t)(dir * HH + u) * BB + b0) = hq;

        // B-fragment-packed h for next step (parity (s+1)&1)
        __nv_bfloat16* Bo = (__nv_bfloat16*)d_Bpack[(s + 1) & 1][dir];
        #pragma unroll
        for (int i = 0; i < 4; i++) {
            int b = b0 + i;
            int nt = b >> 3;
            int lane2 = (b & 7) * 4 + tg2;
            size_t base = ((size_t)(kc2 * 4 + nt) * 32 + lane2) * 4;
            __nv_bfloat16 hi = __float2bfloat16(hv[i]);
            __nv_bfloat16 lo = __float2bfloat16(hv[i] - __bfloat162float(hi));
            Bo[(base + ri2) * 2 + hh2]       = hi;
            Bo[(base + 2 + ri2) * 2 + hh2]   = lo;
        }
        if (s > 0) __syncthreads();   // protect sG reuse next iteration
    }
}

// ---------------- fc + softmax + dihedral ----------------
__global__ void k_fc(const float* __restrict__ fcW, const float* __restrict__ fcb,
                     const float* __restrict__ alphabet)
{
    const int t = blockIdx.x;
    __shared__ float sbuf[256 * BB];
    __shared__ float slog[AA * 33];
    const int tid = threadIdx.x, warp = tid >> 5, lane = tid & 31;

    float acc[8];
    #pragma unroll
    for (int j = 0; j < 8; j++) { int a = warp * 8 + j; acc[j] = (a < AA) ? fcb[a] : 0.f; }

    for (int chunk = 0; chunk < RNN_OUT; chunk += 256) {
        int nk = min(256, RNN_OUT - chunk);
        for (int i = tid; i < nk * BB; i += blockDim.x) {
            int r = chunk + (i >> 5), b = i & 31;
            sbuf[i] = (r < K1) ? d_h1T[(size_t)t * K1 * BB + (size_t)r * BB + b]
                               : d_xT[(size_t)t * 64 * BB + (size_t)(r - K1) * BB + b];
        }
        __syncthreads();
        #pragma unroll
        for (int j = 0; j < 8; j++) {
            int a = warp * 8 + j;
            if (a < AA) {
                const float* wr = fcW + (size_t)a * RNN_OUT + chunk;
                float aj = acc[j];
                for (int k = 0; k < nk; k++) aj = fmaf(__ldg(wr + k), sbuf[k * BB + lane], aj);
                acc[j] = aj;
            }
        }
        __syncthreads();
    }
    #pragma unroll
    for (int j = 0; j < 8; j++) { int a = warp * 8 + j; if (a < AA) slog[a * 33 + lane] = acc[j]; }
    __syncthreads();

    if (tid < BB) {
        int b = tid;
        float mx = -1e30f;
        for (int a = 0; a < AA; a++) mx = fmaxf(mx, slog[a * 33 + b]);
        float sum = 0.f;
        for (int a = 0; a < AA; a++) { float e = expf(slog[a * 33 + b] - mx); slog[a * 33 + b] = e; sum += e; }
        float inv = 1.f / sum;
        float ss0 = 0, ss1 = 0, ss2 = 0, cc0 = 0, cc1 = 0, cc2 = 0;
        for (int a = 0; a < AA; a++) {
            float p = slog[a * 33 + b] * inv;
            float l0 = alphabet[a * 3 + 0], l1 = alphabet[a * 3 + 1], l2 = alphabet[a * 3 + 2];
            ss0 = fmaf(p, sinf(l0), ss0); cc0 = fmaf(p, cosf(l0), cc0);
            ss1 = fmaf(p, sinf(l1), ss1); cc1 = fmaf(p, cosf(l1), cc1);
            ss2 = fmaf(p, sinf(l2), ss2); cc2 = fmaf(p, cosf(l2), cc2);
        }
        d_dih[(t * BB + b) * 3 + 0] = atan2f(ss0, cc0);
        d_dih[(t * BB + b) * 3 + 1] = atan2f(ss1, cc1);
        d_dih[(t * BB + b) * 3 + 2] = atan2f(ss2, cc2);
    }
}

// ---------------- NeRF chain ----------------
struct V3 { float x, y, z; };
__device__ __forceinline__ V3 v3sub(V3 a, V3 b) { return {a.x - b.x, a.y - b.y, a.z - b.z}; }
__device__ __forceinline__ V3 v3cross(V3 a, V3 b) {
    return {a.y * b.z - a.z * b.y, a.z * b.x - a.x * b.z, a.x * b.y - a.y * b.x};
}
__device__ __forceinline__ V3 v3norm(V3 a) {
    float inv = 1.f / sqrtf(a.x * a.x + a.y * a.y + a.z * a.z + 1e-12f);
    return {a.x * inv, a.y * inv, a.z * inv};
}
__global__ void k_nerf(float* __restrict__ out)
{
    int b = threadIdx.x;
    if (b >= BB) return;
    V3 A  = {-0.70710678118654752f, 1.22474487139158905f, 0.f};
    V3 Bv = {-1.41421356237309505f, 0.f, 0.f};
    V3 C  = {0.f, 0.f, 0.f};
    const float bl[3] = {145.801f, 152.326f, 132.868f};
    const float ba[3] = {2.124f, 1.941f, 2.028f};
    float rct[3], rst[3];
    #pragma unroll
    for (int j = 0; j < 3; j++) {
        float th = 3.14159265358979323846f - ba[j];
        rct[j] = bl[j] * cosf(th);
        rst[j] = bl[j] * sinf(th);
    }
    for (int t = 0; t < TT; t++) {
        #pragma unroll
        for (int j = 0; j < 3; j++) {
            float phi = d_dih[(t * BB + b) * 3 + j];
            V3 p = {rct[j], cosf(phi) * rst[j], sinf(phi) * rst[j]};
            V3 bc = v3norm(v3sub(C, Bv));
            V3 n  = v3norm(v3cross(v3sub(Bv, A), bc));
            V3 nx = v3cross(n, bc);
            V3 co = {C.x + p.x * bc.x + p.y * nx.x + p.z * n.x,
                     C.y + p.x * bc.y + p.y * nx.y + p.z * n.y,
                     C.z + p.x * bc.z + p.y * nx.z + p.z * n.z};
            size_t o = ((size_t)(3 * t + j) * BB + b) * 3;
            out[o + 0] = co.x; out[o + 1] = co.y; out[o + 2] = co.z;
            A = Bv; Bv = C; C = co;
        }
    }
}

// ---------------- launch ----------------
extern "C" void kernel_launch(void* const* d_in, const int* in_sizes, int n_in,
                              void* d_out, int out_size)
{
    int base = 2;
    if (base < n_in && in_sizes[base] == 1) base = 3;

    const int*   primary = (const int*)  d_in[0];
    const float* evo     = (const float*)d_in[1];
    const float* emb     = (const float*)d_in[base + 0];
    const float* Wih0f   = (const float*)d_in[base + 1];
    const float* Whh0f   = (const float*)d_in[base + 2];
    const float* b0f     = (const float*)d_in[base + 3];
    const float* Wih0b   = (const float*)d_in[base + 4];
    const float* Whh0b   = (const float*)d_in[base + 5];
    const float* b0b     = (const float*)d_in[base + 6];
    const float* Wih1f   = (const float*)d_in[base + 7];
    const float* Whh1f   = (const float*)d_in[base + 8];
    const float* b1f     = (const float*)d_in[base + 9];
    const float* Wih1b   = (const float*)d_in[base + 10];
    const float* Whh1b   = (const float*)d_in[base + 11];
    const float* b1b     = (const float*)d_in[base + 12];
    const float* fcW     = (const float*)d_in[base + 13];
    const float* fcb     = (const float*)d_in[base + 14];
    const float* alphabet= (const float*)d_in[base + 15];

    const int SMEM_XG1 = K1 * BB * sizeof(float);   // 204800
    cudaFuncSetAttribute((const void*)k_xg<K1, K1, 1>, cudaFuncAttributeMaxDynamicSharedMemorySize, SMEM_XG1);

    k_prep<<<(TT * 64 * BB + 255) / 256, 256>>>(primary, evo, emb);
    k_trans<<<512, 256>>>(Wih0f, Wih0b, Wih1f, Wih1b);
    k_wconv<<<1024, 256>>>(Whh0f, Whh0b, Whh1f, Whh1b);

    dim3 gxg(TT, 2, 1);
    k_xg<DINX, 64, 0><<<gxg, 256, DINX * BB * sizeof(float)>>>(b0f, b0b);
    k_rec<0><<<RGRID, 128>>>();
    k_xg<K1, K1, 1><<<gxg, 256, SMEM_XG1>>>(b1f, b1b);
    k_rec<1><<<RGRID, 128>>>();

    k_fc<<<TT, 256>>>(fcW, fcb, alphabet);
    k_nerf<<<1, 32>>>((float*)d_out);
}

// round 13
// speedup vs baseline: 2.9476x; 2.4033x over previous
#include <cuda_runtime.h>
#include <cuda_bf16.h>
#include <math.h>
#include <stdint.h>

#define TT 700
#define BB 32
#define HH 800
#define K1 1600
#define DINX 53
#define AA 60
#define RNN_OUT 1653
#define RGRID 100

// ---------------- static device buffers ----------------
__device__ float d_xT [TT * 64 * BB];
__device__ float d_h1T[(size_t)TT * K1 * BB];
__device__ float d_xg [(size_t)2 * TT * 3200 * BB];
__device__ float d_Wt0f[DINX * 3200];
__device__ float d_Wt0b[DINX * 3200];
__device__ float d_dih[TT * BB * 3];
// Whh fragments: [layer][dir][wt 0..199][kc 0..49][lane][q 0..7] (q: 4 hi regs, 4 lo regs)
__device__ __align__(16) uint32_t d_Apack[(size_t)2 * 2 * 200 * 50 * 32 * 8];
// Wih1 fragments: [dir][wt 0..199][kc 0..99][lane][q 0..7]
__device__ __align__(16) uint32_t d_Ain1[(size_t)2 * 200 * 100 * 32 * 8];
// B (=h) fragment-packed for recurrent step: [parity][dir][kc 0..49][nt 0..3][lane][4]
__device__ __align__(16) uint32_t d_Bpack[2][2][50 * 4 * 32 * 4];
// h0 fragment-packed per t for k_xgmma: [t][kc 0..99][nt 0..3][lane][4]
__device__ __align__(16) uint32_t d_h0P[(size_t)TT * 100 * 4 * 32 * 4];

// grid barrier (zero-init)
__device__ unsigned g_cnt[8];
__device__ unsigned g_master;
__device__ volatile unsigned g_gen;

// ---------------- mma.sync helper ----------------
__device__ __forceinline__ void mma16816(float& d0, float& d1, float& d2, float& d3,
                                         uint32_t a0, uint32_t a1, uint32_t a2, uint32_t a3,
                                         uint32_t b0, uint32_t b1)
{
    asm volatile("mma.sync.aligned.m16n8k16.row.col.f32.bf16.bf16.f32 "
                 "{%0,%1,%2,%3},{%4,%5,%6,%7},{%8,%9},{%0,%1,%2,%3};"
                 : "+f"(d0), "+f"(d1), "+f"(d2), "+f"(d3)
                 : "r"(a0), "r"(a1), "r"(a2), "r"(a3), "r"(b0), "r"(b1));
}

// ---------------- prep ----------------
__global__ void k_prep(const int* __restrict__ primary, const float* __restrict__ evo,
                       const float* __restrict__ emb)
{
    int idx = blockIdx.x * blockDim.x + threadIdx.x;
    if (idx >= TT * 64 * BB) return;
    int b = idx & 31, k = (idx >> 5) & 63, t = idx >> 11;
    float v = 0.f;
    if (k < 32) v = emb[primary[t * BB + b] * 32 + k];
    else if (k < DINX) v = evo[(t * BB + b) * 21 + (k - 32)];
    d_xT[idx] = v;
}

// ---------------- transpose layer-0 input weights [row][k]->[k][row] ----------------
__global__ void k_trans(const float* __restrict__ W0f, const float* __restrict__ W0b)
{
    const int N0 = 3200 * DINX;
    for (int i = blockIdx.x * blockDim.x + threadIdx.x; i < 2 * N0; i += gridDim.x * blockDim.x) {
        if (i < N0) { int r = i / DINX, k = i % DINX; d_Wt0f[k * 3200 + r] = W0f[i]; }
        else { int j2 = i - N0; int r = j2 / DINX, k = j2 % DINX; d_Wt0b[k * 3200 + r] = W0b[j2]; }
    }
}

// ---------------- pack Whh (both layers) + Wih1 into MMA A-fragment order ----------------
__global__ void k_wconv(const float* __restrict__ Whh0f, const float* __restrict__ Whh0b,
                        const float* __restrict__ Whh1f, const float* __restrict__ Whh1b,
                        const float* __restrict__ Wih1f, const float* __restrict__ Wih1b)
{
    const size_t NT1 = (size_t)2 * 2 * 200 * 50 * 32 * 8;
    for (size_t i = (size_t)blockIdx.x * blockDim.x + threadIdx.x; i < NT1;
         i += (size_t)gridDim.x * blockDim.x) {
        int q = (int)(i & 7);
        size_t r = i >> 3;
        int lane = (int)(r & 31); r >>= 5;
        int kc = (int)(r % 50); r /= 50;
        int wt = (int)(r % 200); r /= 200;
        int dir = (int)(r & 1);
        int layer = (int)(r >> 1);
        int ri = q & 3, pass = q >> 2;
        int gid = lane >> 2, tg = lane & 3;
        int p = wt * 16 + gid + (ri & 1) * 8;
        int u = p >> 2, g = p & 3;
        const float* W = layer ? (dir ? Whh1b : Whh1f) : (dir ? Whh0b : Whh0f);
        const float* wr = W + (size_t)(g * HH + u) * HH;
        uint32_t out = 0;
        #pragma unroll
        for (int hh = 0; hh < 2; hh++) {
            int k = kc * 16 + tg * 2 + hh + ((ri >> 1) & 1) * 8;
            float v = wr[k];
            __nv_bfloat16 hi = __float2bfloat16(v);
            __nv_bfloat16 bv = (pass == 0) ? hi : __float2bfloat16(v - __bfloat162float(hi));
            uint16_t bits = *(uint16_t*)&bv;
            out |= (uint32_t)bits << (hh * 16);
        }
        d_Apack[i] = out;
    }
    const size_t NT2 = (size_t)2 * 200 * 100 * 32 * 8;
    for (size_t i = (size_t)blockIdx.x * blockDim.x + threadIdx.x; i < NT2;
         i += (size_t)gridDim.x * blockDim.x) {
        int q = (int)(i & 7);
        size_t r = i >> 3;
        int lane = (int)(r & 31); r >>= 5;
        int kc = (int)(r % 100); r /= 100;
        int wt = (int)(r % 200); r /= 200;
        int dir = (int)r;
        int ri = q & 3, pass = q >> 2;
        int gid = lane >> 2, tg = lane & 3;
        int p = wt * 16 + gid + (ri & 1) * 8;
        int u = p >> 2, g = p & 3;
        const float* W = dir ? Wih1b : Wih1f;
        const float* wr = W + (size_t)(g * HH + u) * K1;
        uint32_t out = 0;
        #pragma unroll
        for (int hh = 0; hh < 2; hh++) {
            int k = kc * 16 + tg * 2 + hh + ((ri >> 1) & 1) * 8;
            float v = wr[k];
            __nv_bfloat16 hi = __float2bfloat16(v);
            __nv_bfloat16 bv = (pass == 0) ? hi : __float2bfloat16(v - __bfloat162float(hi));
            uint16_t bits = *(uint16_t*)&bv;
            out |= (uint32_t)bits << (hh * 16);
        }
        d_Ain1[i] = out;
    }
}

// ---------------- layer-0 xg (scalar, K=53; small) ----------------
__global__ void k_xg0(const float* __restrict__ bF, const float* __restrict__ bB)
{
    extern __shared__ float sx[];
    const int t = blockIdx.x;
    const int dir = blockIdx.y;
    const float* Wt   = dir ? d_Wt0b : d_Wt0f;
    const float* bias = dir ? bB : bF;
    const float* s0 = d_xT + (size_t)t * 64 * BB;

    for (int i = threadIdx.x; i < DINX * BB / 4; i += blockDim.x)
        ((float4*)sx)[i] = ((const float4*)s0)[i];
    __syncthreads();

    float* out = d_xg + (size_t)(dir * TT + t) * 3200 * BB;
    for (int r = threadIdx.x; r < 3200; r += blockDim.x) {
        float acc[32];
        #pragma unroll
        for (int j = 0; j < 32; j++) acc[j] = 0.f;
        const float* wp = Wt + r;
        for (int k = 0; k < DINX; k++) {
            float w = wp[(size_t)k * 3200];
            const float4* xv = (const float4*)(sx + k * 32);
            #pragma unroll
            for (int j = 0; j < 8; j++) {
                float4 v = xv[j];
                acc[4 * j + 0] = fmaf(w, v.x, acc[4 * j + 0]);
                acc[4 * j + 1] = fmaf(w, v.y, acc[4 * j + 1]);
                acc[4 * j + 2] = fmaf(w, v.z, acc[4 * j + 2]);
                acc[4 * j + 3] = fmaf(w, v.w, acc[4 * j + 3]);
            }
        }
        float bv = bias[r];
        float4* op = (float4*)(out + (size_t)r * BB);
        #pragma unroll
        for (int j = 0; j < 8; j++) {
            float4 v4 = {acc[4*j+0] + bv, acc[4*j+1] + bv, acc[4*j+2] + bv, acc[4*j+3] + bv};
            op[j] = v4;
        }
    }
}

// ---------------- layer-1 xg via mma.sync: xg = Wih1 * h0 + bias ----------------
// grid (700, 25, 2): block = (t, mtile of 128 rows, dir); 4 warps x 2 wt each.
__global__ void __launch_bounds__(128, 1) k_xgmma(const float* __restrict__ b1f,
                                                  const float* __restrict__ b1b)
{
    const int t = blockIdx.x;
    const int mt = blockIdx.y;
    const int dir = blockIdx.z;
    const int w = threadIdx.x >> 5, lane = threadIdx.x & 31;
    const int gid = lane >> 2, tg = lane & 3;
    const float* bias = dir ? b1b : b1f;

    const uint4* Bb = (const uint4*)d_h0P + (size_t)t * (100 * 4 * 32);
    const int wt0 = mt * 8 + w * 2;
    const uint4* A0 = (const uint4*)d_Ain1 + ((size_t)(dir * 200 + wt0)) * 100 * 32 * 2;
    const uint4* A1 = A0 + (size_t)100 * 32 * 2;

    float C[2][4][4];
    #pragma unroll
    for (int q = 0; q < 2; q++)
        #pragma unroll
        for (int nt = 0; nt < 4; nt++)
            #pragma unroll
            for (int i = 0; i < 4; i++) C[q][nt][i] = 0.f;

    #pragma unroll 2
    for (int kc = 0; kc < 100; kc++) {
        uint4 a0h = A0[(kc * 32 + lane) * 2];
        uint4 a0l = A0[(kc * 32 + lane) * 2 + 1];
        uint4 a1h = A1[(kc * 32 + lane) * 2];
        uint4 a1l = A1[(kc * 32 + lane) * 2 + 1];
        #pragma unroll
        for (int nt = 0; nt < 4; nt++) {
            uint4 bf = Bb[(kc * 4 + nt) * 32 + lane];
            mma16816(C[0][nt][0], C[0][nt][1], C[0][nt][2], C[0][nt][3],
                     a0h.x, a0h.y, a0h.z, a0h.w, bf.x, bf.y);
            mma16816(C[0][nt][0], C[0][nt][1], C[0][nt][2], C[0][nt][3],
                     a0l.x, a0l.y, a0l.z, a0l.w, bf.x, bf.y);
            mma16816(C[0][nt][0], C[0][nt][1], C[0][nt][2], C[0][nt][3],
                     a0h.x, a0h.y, a0h.z, a0h.w, bf.z, bf.w);
            mma16816(C[1][nt][0], C[1][nt][1], C[1][nt][2], C[1][nt][3],
                     a1h.x, a1h.y, a1h.z, a1h.w, bf.x, bf.y);
            mma16816(C[1][nt][0], C[1][nt][1], C[1][nt][2], C[1][nt][3],
                     a1l.x, a1l.y, a1l.z, a1l.w, bf.x, bf.y);
            mma16816(C[1][nt][0], C[1][nt][1], C[1][nt][2], C[1][nt][3],
                     a1h.x, a1h.y, a1h.z, a1h.w, bf.z, bf.w);
        }
    }

    float* out = d_xg + (size_t)(dir * TT + t) * 3200 * BB;
    #pragma unroll
    for (int q = 0; q < 2; q++) {
        int wt = wt0 + q;
        #pragma unroll
        for (int half = 0; half < 2; half++) {
            int p = wt * 16 + gid + half * 8;
            int u = p >> 2, g = p & 3;
            int r = g * HH + u;
            float bv = __ldg(bias + r);
            float* orow = out + (size_t)r * BB;
            #pragma unroll
            for (int nt = 0; nt < 4; nt++) {
                int col = nt * 8 + tg * 2;
                float2 v = {C[q][nt][half * 2 + 0] + bv, C[q][nt][half * 2 + 1] + bv};
                *(float2*)(orow + col) = v;
            }
        }
    }
}

// ---------------- hierarchical 100-CTA barrier ----------------
__device__ __forceinline__ void gsync100(unsigned& mygen)
{
    __syncthreads();
    if (threadIdx.x == 0) {
        __threadfence();
        int grp = blockIdx.x & 7;
        unsigned sz = (grp < 4) ? 13u : 12u;   // 100 = 4*13 + 4*12
        unsigned v = atomicAdd(&g_cnt[grp], 1u);
        if (v == sz - 1u) {
            g_cnt[grp] = 0u;
            __threadfence();
            unsigned m = atomicAdd(&g_master, 1u);
            if (m == 7u) {
                g_master = 0u;
                __threadfence();
                g_gen = mygen + 1u;
            }
        }
        while (g_gen == mygen) { }
        __threadfence();
    }
    __syncthreads();
    mygen++;
}

// ---------------- persistent mma.sync recurrent layer (split-K, 8 warps) ----------------
// 100 CTAs: dir = bid&1, jt = bid>>1 (0..49) -> 64 permuted gate-rows = 16 units x 4 gates.
// warps 0-3: wt = jt*4+w, kc 0..24; warps 4-7: same wt, kc 25..49; smem reduce.
template <int LAYER>
__global__ void __launch_bounds__(256, 1) k_rec()
{
    __shared__ float sG[64 * 33];
    __shared__ float sR[64 * 33];
    const int tid = threadIdx.x;
    const int w = tid >> 5, lane = tid & 31;
    const int dir = blockIdx.x & 1;
    const int jt = blockIdx.x >> 1;
    const int wtl = w & 3;
    const int wt = jt * 4 + wtl;
    const int kh = w >> 2;
    const int gid = lane >> 2, tg = lane & 3;

    const uint4* Abase = (const uint4*)d_Apack
        + ((size_t)((LAYER * 2 + dir) * 200 + wt)) * 50 * 32 * 2
        + (size_t)kh * 25 * 32 * 2;

    // epilogue mapping: thread -> (unit u, batches b0..b0+1)
    const int ul = tid >> 4;
    const int b0 = (tid & 15) * 2;
    const int u = jt * 16 + ul;
    const int kc2 = u >> 4, kl = u & 15;
    const int ri2 = kl >> 3, rem = kl & 7, tg2 = rem >> 1, hh2 = rem & 1;

    unsigned mygen = g_gen;
    float cs[2] = {0.f, 0.f};

    for (int s = 0; s < TT; s++) {
        const int t = dir ? (TT - 1 - s) : s;
        if (s > 0) {
            gsync100(mygen);
            const uint4* Bb = (const uint4*)d_Bpack[s & 1][dir] + (size_t)kh * 25 * 4 * 32;
            float C[4][4];
            #pragma unroll
            for (int nt = 0; nt < 4; nt++)
                #pragma unroll
                for (int i = 0; i < 4; i++) C[nt][i] = 0.f;

            #pragma unroll 2
            for (int kc = 0; kc < 25; kc++) {
                uint4 ahi = Abase[(kc * 32 + lane) * 2];
                uint4 alo = Abase[(kc * 32 + lane) * 2 + 1];
                #pragma unroll
                for (int nt = 0; nt < 4; nt++) {
                    uint4 bf = Bb[(kc * 4 + nt) * 32 + lane];
                    mma16816(C[nt][0], C[nt][1], C[nt][2], C[nt][3],
                             ahi.x, ahi.y, ahi.z, ahi.w, bf.x, bf.y);
                    mma16816(C[nt][0], C[nt][1], C[nt][2], C[nt][3],
                             alo.x, alo.y, alo.z, alo.w, bf.x, bf.y);
                    mma16816(C[nt][0], C[nt][1], C[nt][2], C[nt][3],
                             ahi.x, ahi.y, ahi.z, ahi.w, bf.z, bf.w);
                }
            }
            const int lr = wtl * 16 + gid;
            if (kh == 1) {
                #pragma unroll
                for (int nt = 0; nt < 4; nt++) {
                    int col = nt * 8 + tg * 2;
                    sR[lr * 33 + col]           = C[nt][0];
                    sR[lr * 33 + col + 1]       = C[nt][1];
                    sR[(lr + 8) * 33 + col]     = C[nt][2];
                    sR[(lr + 8) * 33 + col + 1] = C[nt][3];
                }
            }
            __syncthreads();
            if (kh == 0) {
                #pragma unroll
                for (int nt = 0; nt < 4; nt++) {
                    int col = nt * 8 + tg * 2;
                    sG[lr * 33 + col]           = C[nt][0] + sR[lr * 33 + col];
                    sG[lr * 33 + col + 1]       = C[nt][1] + sR[lr * 33 + col + 1];
                    sG[(lr + 8) * 33 + col]     = C[nt][2] + sR[(lr + 8) * 33 + col];
                    sG[(lr + 8) * 33 + col + 1] = C[nt][3] + sR[(lr + 8) * 33 + col + 1];
                }
            }
            __syncthreads();
        }

        // epilogue
        const float* xg = d_xg + (size_t)(dir * TT + t) * 3200 * BB;
        float2 xv0 = *(const float2*)(xg + (size_t)(0 * HH + u) * BB + b0);
        float2 xv1 = *(const float2*)(xg + (size_t)(1 * HH + u) * BB + b0);
        float2 xv2 = *(const float2*)(xg + (size_t)(2 * HH + u) * BB + b0);
        float2 xv3 = *(const float2*)(xg + (size_t)(3 * HH + u) * BB + b0);
        float hv[2];
        #pragma unroll
        for (int i = 0; i < 2; i++) {
            int b = b0 + i;
            float p0 = (i == 0) ? xv0.x : xv0.y;
            float p1 = (i == 0) ? xv1.x : xv1.y;
            float p2 = (i == 0) ? xv2.x : xv2.y;
            float p3 = (i == 0) ? xv3.x : xv3.y;
            if (s > 0) {
                p0 += sG[(ul * 4 + 0) * 33 + b];
                p1 += sG[(ul * 4 + 1) * 33 + b];
                p2 += sG[(ul * 4 + 2) * 33 + b];
                p3 += sG[(ul * 4 + 3) * 33 + b];
            }
            float ig = 1.f / (1.f + expf(-p0));
            float fg = 1.f / (1.f + expf(-p1));
            float gg = tanhf(p2);
            float og = 1.f / (1.f + expf(-p3));
            cs[i] = (s == 0) ? (ig * gg) : (fg * cs[i] + ig * gg);
            hv[i] = og * tanhf(cs[i]);
        }
        if (LAYER == 1) {
            float2 hq = {hv[0], hv[1]};
            *(float2*)(d_h1T + (size_t)t * (K1 * BB) + (size_t)(dir * HH + u) * BB + b0) = hq;
        }

        // fragment-packed h: Bpack (next step) and, for layer 0, d_h0P[t] (for k_xgmma)
        __nv_bfloat16* Bo = (__nv_bfloat16*)d_Bpack[(s + 1) & 1][dir];
        __nv_bfloat16* Po = (__nv_bfloat16*)(d_h0P + (size_t)t * (100 * 4 * 32 * 4));
        #pragma unroll
        for (int i = 0; i < 2; i++) {
            int b = b0 + i;
            int nt = b >> 3;
            int lane2 = (b & 7) * 4 + tg2;
            __nv_bfloat16 hi = __float2bfloat16(hv[i]);
            __nv_bfloat16 lo = __float2bfloat16(hv[i] - __bfloat162float(hi));
            size_t base = ((size_t)(kc2 * 4 + nt) * 32 + lane2) * 4;
            Bo[(base + ri2) * 2 + hh2]     = hi;
            Bo[(base + 2 + ri2) * 2 + hh2] = lo;
            if (LAYER == 0) {
                size_t baseg = ((size_t)((dir * 50 + kc2) * 4 + nt) * 32 + lane2) * 4;
                Po[(baseg + ri2) * 2 + hh2]     = hi;
                Po[(baseg + 2 + ri2) * 2 + hh2] = lo;
            }
        }
    }
}

// ---------------- fc + softmax + dihedral ----------------
__global__ void k_fc(const float* __restrict__ fcW, const float* __restrict__ fcb,
                     const float* __restrict__ alphabet)
{
    const int t = blockIdx.x;
    __shared__ float sbuf[256 * BB];
    __shared__ float slog[AA * 33];
    const int tid = threadIdx.x, warp = tid >> 5, lane = tid & 31;

    float acc[8];
    #pragma unroll
    for (int j = 0; j < 8; j++) { int a = warp * 8 + j; acc[j] = (a < AA) ? fcb[a] : 0.f; }

    for (int chunk = 0; chunk < RNN_OUT; chunk += 256) {
        int nk = min(256, RNN_OUT - chunk);
        for (int i = tid; i < nk * BB; i += blockDim.x) {
            int r = chunk + (i >> 5), b = i & 31;
            sbuf[i] = (r < K1) ? d_h1T[(size_t)t * K1 * BB + (size_t)r * BB + b]
                               : d_xT[(size_t)t * 64 * BB + (size_t)(r - K1) * BB + b];
        }
        __syncthreads();
        #pragma unroll
        for (int j = 0; j < 8; j++) {
            int a = warp * 8 + j;
            if (a < AA) {
                const float* wr = fcW + (size_t)a * RNN_OUT + chunk;
                float aj = acc[j];
                for (int k = 0; k < nk; k++) aj = fmaf(__ldg(wr + k), sbuf[k * BB + lane], aj);
                acc[j] = aj;
            }
        }
        __syncthreads();
    }
    #pragma unroll
    for (int j = 0; j < 8; j++) { int a = warp * 8 + j; if (a < AA) slog[a * 33 + lane] = acc[j]; }
    __syncthreads();

    if (tid < BB) {
        int b = tid;
        float mx = -1e30f;
        for (int a = 0; a < AA; a++) mx = fmaxf(mx, slog[a * 33 + b]);
        float sum = 0.f;
        for (int a = 0; a < AA; a++) { float e = expf(slog[a * 33 + b] - mx); slog[a * 33 + b] = e; sum += e; }
        float inv = 1.f / sum;
        float ss0 = 0, ss1 = 0, ss2 = 0, cc0 = 0, cc1 = 0, cc2 = 0;
        for (int a = 0; a < AA; a++) {
            float p = slog[a * 33 + b] * inv;
            float l0 = alphabet[a * 3 + 0], l1 = alphabet[a * 3 + 1], l2 = alphabet[a * 3 + 2];
            ss0 = fmaf(p, sinf(l0), ss0); cc0 = fmaf(p, cosf(l0), cc0);
            ss1 = fmaf(p, sinf(l1), ss1); cc1 = fmaf(p, cosf(l1), cc1);
            ss2 = fmaf(p, sinf(l2), ss2); cc2 = fmaf(p, cosf(l2), cc2);
        }
        d_dih[(t * BB + b) * 3 + 0] = atan2f(ss0, cc0);
        d_dih[(t * BB + b) * 3 + 1] = atan2f(ss1, cc1);
        d_dih[(t * BB + b) * 3 + 2] = atan2f(ss2, cc2);
    }
}

// ---------------- NeRF chain ----------------
struct V3 { float x, y, z; };
__device__ __forceinline__ V3 v3sub(V3 a, V3 b) { return {a.x - b.x, a.y - b.y, a.z - b.z}; }
__device__ __forceinline__ V3 v3cross(V3 a, V3 b) {
    return {a.y * b.z - a.z * b.y, a.z * b.x - a.x * b.z, a.x * b.y - a.y * b.x};
}
__device__ __forceinline__ V3 v3norm(V3 a) {
    float inv = 1.f / sqrtf(a.x * a.x + a.y * a.y + a.z * a.z + 1e-12f);
    return {a.x * inv, a.y * inv, a.z * inv};
}
__global__ void k_nerf(float* __restrict__ out)
{
    int b = threadIdx.x;
    if (b >= BB) return;
    V3 A  = {-0.70710678118654752f, 1.22474487139158905f, 0.f};
    V3 Bv = {-1.41421356237309505f, 0.f, 0.f};
    V3 C  = {0.f, 0.f, 0.f};
    const float bl[3] = {145.801f, 152.326f, 132.868f};
    const float ba[3] = {2.124f, 1.941f, 2.028f};
    float rct[3], rst[3];
    #pragma unroll
    for (int j = 0; j < 3; j++) {
        float th = 3.14159265358979323846f - ba[j];
        rct[j] = bl[j] * cosf(th);
        rst[j] = bl[j] * sinf(th);
    }
    for (int t = 0; t < TT; t++) {
        #pragma unroll
        for (int j = 0; j < 3; j++) {
            float phi = d_dih[(t * BB + b) * 3 + j];
            V3 p = {rct[j], cosf(phi) * rst[j], sinf(phi) * rst[j]};
            V3 bc = v3norm(v3sub(C, Bv));
            V3 n  = v3norm(v3cross(v3sub(Bv, A), bc));
            V3 nx = v3cross(n, bc);
            V3 co = {C.x + p.x * bc.x + p.y * nx.x + p.z * n.x,
                     C.y + p.x * bc.y + p.y * nx.y + p.z * n.y,
                     C.z + p.x * bc.z + p.y * nx.z + p.z * n.z};
            size_t o = ((size_t)(3 * t + j) * BB + b) * 3;
            out[o + 0] = co.x; out[o + 1] = co.y; out[o + 2] = co.z;
            A = Bv; Bv = C; C = co;
        }
    }
}

// ---------------- launch ----------------
extern "C" void kernel_launch(void* const* d_in, const int* in_sizes, int n_in,
                              void* d_out, int out_size)
{
    int base = 2;
    if (base < n_in && in_sizes[base] == 1) base = 3;

    const int*   primary = (const int*)  d_in[0];
    const float* evo     = (const float*)d_in[1];
    const float* emb     = (const float*)d_in[base + 0];
    const float* Wih0f   = (const float*)d_in[base + 1];
    const float* Whh0f   = (const float*)d_in[base + 2];
    const float* b0f     = (const float*)d_in[base + 3];
    const float* Wih0b   = (const float*)d_in[base + 4];
    const float* Whh0b   = (const float*)d_in[base + 5];
    const float* b0b     = (const float*)d_in[base + 6];
    const float* Wih1f   = (const float*)d_in[base + 7];
    const float* Whh1f   = (const float*)d_in[base + 8];
    const float* b1f     = (const float*)d_in[base + 9];
    const float* Wih1b   = (const float*)d_in[base + 10];
    const float* Whh1b   = (const float*)d_in[base + 11];
    const float* b1b     = (const float*)d_in[base + 12];
    const float* fcW     = (const float*)d_in[base + 13];
    const float* fcb     = (const float*)d_in[base + 14];
    const float* alphabet= (const float*)d_in[base + 15];

    k_prep<<<(TT * 64 * BB + 255) / 256, 256>>>(primary, evo, emb);
    k_trans<<<256, 256>>>(Wih0f, Wih0b);
    k_wconv<<<1024, 256>>>(Whh0f, Whh0b, Whh1f, Whh1b, Wih1f, Wih1b);

    dim3 gxg0(TT, 2, 1);
    k_xg0<<<gxg0, 256, DINX * BB * sizeof(float)>>>(b0f, b0b);
    k_rec<0><<<RGRID, 256>>>();
    dim3 gmm(TT, 25, 2);
    k_xgmma<<<gmm, 128>>>(b1f, b1b);
    k_rec<1><<<RGRID, 256>>>();

    k_fc<<<TT, 256>>>(fcW, fcb, alphabet);
    k_nerf<<<1, 32>>>((float*)d_out);
}

// round 14
// speedup vs baseline: 4.2244x; 1.4332x over previous
#include <cuda_runtime.h>
#include <cuda_bf16.h>
#include <math.h>
#include <stdint.h>

#define TT 700
#define BB 32
#define HH 800
#define K1 1600
#define DINX 53
#define AA 60
#define RNN_OUT 1653
#define RGRID 100

// ---------------- static device buffers ----------------
__device__ float d_xT [TT * 64 * BB];
__device__ float d_h1T[(size_t)TT * K1 * BB];
__device__ float d_xg [(size_t)2 * TT * 3200 * BB];
__device__ float d_Wt0f[DINX * 3200];
__device__ float d_Wt0b[DINX * 3200];
__device__ float d_dih[TT * BB * 3];
// Whh fragments: [layer][dir][wt 0..199][kc 0..49][lane][q 0..7] (q: 4 hi regs, 4 lo regs)
__device__ __align__(16) uint32_t d_Apack[(size_t)2 * 2 * 200 * 50 * 32 * 8];
// Wih1 fragments: [dir][wt 0..199][kc 0..99][lane][q 0..7]
__device__ __align__(16) uint32_t d_Ain1[(size_t)2 * 200 * 100 * 32 * 8];
// B (=h) fragment-packed for recurrent step: [parity][dir][kc 0..49][nt 0..3][lane][4]
__device__ __align__(16) uint32_t d_Bpack[2][2][50 * 4 * 32 * 4];
// h0 fragment-packed per t for k_xgmma: [t][kc 0..99][nt 0..3][lane][4]
__device__ __align__(16) uint32_t d_h0P[(size_t)TT * 100 * 4 * 32 * 4];

// grid barrier (zero-init)
__device__ unsigned g_cnt[8];
__device__ unsigned g_master;
__device__ volatile unsigned g_gen;

// ---------------- mma.sync helper ----------------
__device__ __forceinline__ void mma16816(float& d0, float& d1, float& d2, float& d3,
                                         uint32_t a0, uint32_t a1, uint32_t a2, uint32_t a3,
                                         uint32_t b0, uint32_t b1)
{
    asm volatile("mma.sync.aligned.m16n8k16.row.col.f32.bf16.bf16.f32 "
                 "{%0,%1,%2,%3},{%4,%5,%6,%7},{%8,%9},{%0,%1,%2,%3};"
                 : "+f"(d0), "+f"(d1), "+f"(d2), "+f"(d3)
                 : "r"(a0), "r"(a1), "r"(a2), "r"(a3), "r"(b0), "r"(b1));
}

// ---------------- prep ----------------
__global__ void k_prep(const int* __restrict__ primary, const float* __restrict__ evo,
                       const float* __restrict__ emb)
{
    int idx = blockIdx.x * blockDim.x + threadIdx.x;
    if (idx >= TT * 64 * BB) return;
    int b = idx & 31, k = (idx >> 5) & 63, t = idx >> 11;
    float v = 0.f;
    if (k < 32) v = emb[primary[t * BB + b] * 32 + k];
    else if (k < DINX) v = evo[(t * BB + b) * 21 + (k - 32)];
    d_xT[idx] = v;
}

// ---------------- transpose layer-0 input weights [row][k]->[k][row] ----------------
__global__ void k_trans(const float* __restrict__ W0f, const float* __restrict__ W0b)
{
    const int N0 = 3200 * DINX;
    for (int i = blockIdx.x * blockDim.x + threadIdx.x; i < 2 * N0; i += gridDim.x * blockDim.x) {
        if (i < N0) { int r = i / DINX, k = i % DINX; d_Wt0f[k * 3200 + r] = W0f[i]; }
        else { int j2 = i - N0; int r = j2 / DINX, k = j2 % DINX; d_Wt0b[k * 3200 + r] = W0b[j2]; }
    }
}

// ---------------- pack Whh (both layers) + Wih1 into MMA A-fragment order ----------------
__global__ void k_wconv(const float* __restrict__ Whh0f, const float* __restrict__ Whh0b,
                        const float* __restrict__ Whh1f, const float* __restrict__ Whh1b,
                        const float* __restrict__ Wih1f, const float* __restrict__ Wih1b)
{
    const size_t NT1 = (size_t)2 * 2 * 200 * 50 * 32 * 8;
    for (size_t i = (size_t)blockIdx.x * blockDim.x + threadIdx.x; i < NT1;
         i += (size_t)gridDim.x * blockDim.x) {
        int q = (int)(i & 7);
        size_t r = i >> 3;
        int lane = (int)(r & 31); r >>= 5;
        int kc = (int)(r % 50); r /= 50;
        int wt = (int)(r % 200); r /= 200;
        int dir = (int)(r & 1);
        int layer = (int)(r >> 1);
        int ri = q & 3, pass = q >> 2;
        int gid = lane >> 2, tg = lane & 3;
        int p = wt * 16 + gid + (ri & 1) * 8;
        int u = p >> 2, g = p & 3;
        const float* W = layer ? (dir ? Whh1b : Whh1f) : (dir ? Whh0b : Whh0f);
        const float* wr = W + (size_t)(g * HH + u) * HH;
        uint32_t out = 0;
        #pragma unroll
        for (int hh = 0; hh < 2; hh++) {
            int k = kc * 16 + tg * 2 + hh + ((ri >> 1) & 1) * 8;
            float v = wr[k];
            __nv_bfloat16 hi = __float2bfloat16(v);
            __nv_bfloat16 bv = (pass == 0) ? hi : __float2bfloat16(v - __bfloat162float(hi));
            uint16_t bits = *(uint16_t*)&bv;
            out |= (uint32_t)bits << (hh * 16);
        }
        d_Apack[i] = out;
    }
    const size_t NT2 = (size_t)2 * 200 * 100 * 32 * 8;
    for (size_t i = (size_t)blockIdx.x * blockDim.x + threadIdx.x; i < NT2;
         i += (size_t)gridDim.x * blockDim.x) {
        int q = (int)(i & 7);
        size_t r = i >> 3;
        int lane = (int)(r & 31); r >>= 5;
        int kc = (int)(r % 100); r /= 100;
        int wt = (int)(r % 200); r /= 200;
        int dir = (int)r;
        int ri = q & 3, pass = q >> 2;
        int gid = lane >> 2, tg = lane & 3;
        int p = wt * 16 + gid + (ri & 1) * 8;
        int u = p >> 2, g = p & 3;
        const float* W = dir ? Wih1b : Wih1f;
        const float* wr = W + (size_t)(g * HH + u) * K1;
        uint32_t out = 0;
        #pragma unroll
        for (int hh = 0; hh < 2; hh++) {
            int k = kc * 16 + tg * 2 + hh + ((ri >> 1) & 1) * 8;
            float v = wr[k];
            __nv_bfloat16 hi = __float2bfloat16(v);
            __nv_bfloat16 bv = (pass == 0) ? hi : __float2bfloat16(v - __bfloat162float(hi));
            uint16_t bits = *(uint16_t*)&bv;
            out |= (uint32_t)bits << (hh * 16);
        }
        d_Ain1[i] = out;
    }
}

// ---------------- layer-0 xg (scalar, K=53; small) ----------------
__global__ void k_xg0(const float* __restrict__ bF, const float* __restrict__ bB)
{
    extern __shared__ float sx[];
    const int t = blockIdx.x;
    const int dir = blockIdx.y;
    const float* Wt   = dir ? d_Wt0b : d_Wt0f;
    const float* bias = dir ? bB : bF;
    const float* s0 = d_xT + (size_t)t * 64 * BB;

    for (int i = threadIdx.x; i < DINX * BB / 4; i += blockDim.x)
        ((float4*)sx)[i] = ((const float4*)s0)[i];
    __syncthreads();

    float* out = d_xg + (size_t)(dir * TT + t) * 3200 * BB;
    for (int r = threadIdx.x; r < 3200; r += blockDim.x) {
        float acc[32];
        #pragma unroll
        for (int j = 0; j < 32; j++) acc[j] = 0.f;
        const float* wp = Wt + r;
        for (int k = 0; k < DINX; k++) {
            float w = wp[(size_t)k * 3200];
            const float4* xv = (const float4*)(sx + k * 32);
            #pragma unroll
            for (int j = 0; j < 8; j++) {
                float4 v = xv[j];
                acc[4 * j + 0] = fmaf(w, v.x, acc[4 * j + 0]);
                acc[4 * j + 1] = fmaf(w, v.y, acc[4 * j + 1]);
                acc[4 * j + 2] = fmaf(w, v.z, acc[4 * j + 2]);
                acc[4 * j + 3] = fmaf(w, v.w, acc[4 * j + 3]);
            }
        }
        float bv = bias[r];
        float4* op = (float4*)(out + (size_t)r * BB);
        #pragma unroll
        for (int j = 0; j < 8; j++) {
            float4 v4 = {acc[4*j+0] + bv, acc[4*j+1] + bv, acc[4*j+2] + bv, acc[4*j+3] + bv};
            op[j] = v4;
        }
    }
}

// ---------------- layer-1 xg via mma.sync: xg = Wih1 * h0 + bias ----------------
__global__ void __launch_bounds__(128, 1) k_xgmma(const float* __restrict__ b1f,
                                                  const float* __restrict__ b1b)
{
    const int t = blockIdx.x;
    const int mt = blockIdx.y;
    const int dir = blockIdx.z;
    const int w = threadIdx.x >> 5, lane = threadIdx.x & 31;
    const int gid = lane >> 2, tg = lane & 3;
    const float* bias = dir ? b1b : b1f;

    const uint4* Bb = (const uint4*)d_h0P + (size_t)t * (100 * 4 * 32);
    const int wt0 = mt * 8 + w * 2;
    const uint4* A0 = (const uint4*)d_Ain1 + ((size_t)(dir * 200 + wt0)) * 100 * 32 * 2;
    const uint4* A1 = A0 + (size_t)100 * 32 * 2;

    float C[2][4][4];
    #pragma unroll
    for (int q = 0; q < 2; q++)
        #pragma unroll
        for (int nt = 0; nt < 4; nt++)
            #pragma unroll
            for (int i = 0; i < 4; i++) C[q][nt][i] = 0.f;

    #pragma unroll 2
    for (int kc = 0; kc < 100; kc++) {
        uint4 a0h = A0[(kc * 32 + lane) * 2];
        uint4 a0l = A0[(kc * 32 + lane) * 2 + 1];
        uint4 a1h = A1[(kc * 32 + lane) * 2];
        uint4 a1l = A1[(kc * 32 + lane) * 2 + 1];
        #pragma unroll
        for (int nt = 0; nt < 4; nt++) {
            uint4 bf = Bb[(kc * 4 + nt) * 32 + lane];
            mma16816(C[0][nt][0], C[0][nt][1], C[0][nt][2], C[0][nt][3],
                     a0h.x, a0h.y, a0h.z, a0h.w, bf.x, bf.y);
            mma16816(C[0][nt][0], C[0][nt][1], C[0][nt][2], C[0][nt][3],
                     a0l.x, a0l.y, a0l.z, a0l.w, bf.x, bf.y);
            mma16816(C[0][nt][0], C[0][nt][1], C[0][nt][2], C[0][nt][3],
                     a0h.x, a0h.y, a0h.z, a0h.w, bf.z, bf.w);
            mma16816(C[1][nt][0], C[1][nt][1], C[1][nt][2], C[1][nt][3],
                     a1h.x, a1h.y, a1h.z, a1h.w, bf.x, bf.y);
            mma16816(C[1][nt][0], C[1][nt][1], C[1][nt][2], C[1][nt][3],
                     a1l.x, a1l.y, a1l.z, a1l.w, bf.x, bf.y);
            mma16816(C[1][nt][0], C[1][nt][1], C[1][nt][2], C[1][nt][3],
                     a1h.x, a1h.y, a1h.z, a1h.w, bf.z, bf.w);
        }
    }

    float* out = d_xg + (size_t)(dir * TT + t) * 3200 * BB;
    #pragma unroll
    for (int q = 0; q < 2; q++) {
        int wt = wt0 + q;
        #pragma unroll
        for (int half = 0; half < 2; half++) {
            int p = wt * 16 + gid + half * 8;
            int u = p >> 2, g = p & 3;
            int r = g * HH + u;
            float bv = __ldg(bias + r);
            float* orow = out + (size_t)r * BB;
            #pragma unroll
            for (int nt = 0; nt < 4; nt++) {
                int col = nt * 8 + tg * 2;
                float2 v = {C[q][nt][half * 2 + 0] + bv, C[q][nt][half * 2 + 1] + bv};
                *(float2*)(orow + col) = v;
            }
        }
    }
}

// ---------------- hierarchical 100-CTA barrier ----------------
__device__ __forceinline__ void gsync100(unsigned& mygen)
{
    __syncthreads();
    if (threadIdx.x == 0) {
        __threadfence();
        int grp = blockIdx.x & 7;
        unsigned sz = (grp < 4) ? 13u : 12u;   // 100 = 4*13 + 4*12
        unsigned v = atomicAdd(&g_cnt[grp], 1u);
        if (v == sz - 1u) {
            g_cnt[grp] = 0u;
            __threadfence();
            unsigned m = atomicAdd(&g_master, 1u);
            if (m == 7u) {
                g_master = 0u;
                __threadfence();
                g_gen = mygen + 1u;
            }
        }
        while (g_gen == mygen) { }
        __threadfence();
    }
    __syncthreads();
    mygen++;
}

// ---------------- persistent mma.sync recurrent layer (split-K, 8 warps, smem-resident A) ----------------
// smem: [0, 204800) A fragments (4 wt x 50 kc x 32 lanes x 2 uint4)
//       [204800, 213248) sG   [213248, 221696) sR
#define SMA_BYTES 204800
#define SMEM_REC (SMA_BYTES + 2 * 64 * 33 * 4)

template <int LAYER>
__global__ void __launch_bounds__(256, 1) k_rec()
{
    extern __shared__ __align__(16) unsigned char smrec[];
    uint4* smA = (uint4*)smrec;
    float* sG = (float*)(smrec + SMA_BYTES);
    float* sR = sG + 64 * 33;

    const int tid = threadIdx.x;
    const int w = tid >> 5, lane = tid & 31;
    const int dir = blockIdx.x & 1;
    const int jt = blockIdx.x >> 1;
    const int wtl = w & 3;
    const int kh = w >> 2;
    const int gid = lane >> 2, tg = lane & 3;

    // load this CTA's A slice once (4 wt contiguous in d_Apack)
    {
        const uint4* Asrc = (const uint4*)d_Apack
            + ((size_t)((LAYER * 2 + dir) * 200 + jt * 4)) * 50 * 32 * 2;
        for (int i = tid; i < 4 * 50 * 32 * 2; i += 256) smA[i] = Asrc[i];
    }
    __syncthreads();

    const uint4* Aw = smA + ((size_t)(wtl * 50 + kh * 25)) * 32 * 2;

    // epilogue mapping: thread -> (unit u, batches b0..b0+1)
    const int ul = tid >> 4;
    const int b0 = (tid & 15) * 2;
    const int u = jt * 16 + ul;
    const int kc2 = u >> 4, kl = u & 15;
    const int ri2 = kl >> 3, rem = kl & 7, tg2 = rem >> 1, hh2 = rem & 1;

    unsigned mygen = g_gen;
    float cs[2] = {0.f, 0.f};

    for (int s = 0; s < TT; s++) {
        const int t = dir ? (TT - 1 - s) : s;
        if (s > 0) {
            gsync100(mygen);
            const uint4* Bb = (const uint4*)d_Bpack[s & 1][dir] + (size_t)kh * 25 * 4 * 32;
            float C[4][4];
            #pragma unroll
            for (int nt = 0; nt < 4; nt++)
                #pragma unroll
                for (int i = 0; i < 4; i++) C[nt][i] = 0.f;

            #pragma unroll 2
            for (int kc = 0; kc < 25; kc++) {
                uint4 ahi = Aw[(kc * 32 + lane) * 2];
                uint4 alo = Aw[(kc * 32 + lane) * 2 + 1];
                #pragma unroll
                for (int nt = 0; nt < 4; nt++) {
                    uint4 bf = Bb[(kc * 4 + nt) * 32 + lane];
                    mma16816(C[nt][0], C[nt][1], C[nt][2], C[nt][3],
                             ahi.x, ahi.y, ahi.z, ahi.w, bf.x, bf.y);
                    mma16816(C[nt][0], C[nt][1], C[nt][2], C[nt][3],
                             alo.x, alo.y, alo.z, alo.w, bf.x, bf.y);
                    mma16816(C[nt][0], C[nt][1], C[nt][2], C[nt][3],
                             ahi.x, ahi.y, ahi.z, ahi.w, bf.z, bf.w);
                }
            }
            const int lr = wtl * 16 + gid;
            if (kh == 1) {
                #pragma unroll
                for (int nt = 0; nt < 4; nt++) {
                    int col = nt * 8 + tg * 2;
                    sR[lr * 33 + col]           = C[nt][0];
                    sR[lr * 33 + col + 1]       = C[nt][1];
                    sR[(lr + 8) * 33 + col]     = C[nt][2];
                    sR[(lr + 8) * 33 + col + 1] = C[nt][3];
                }
            }
            __syncthreads();
            if (kh == 0) {
                #pragma unroll
                for (int nt = 0; nt < 4; nt++) {
                    int col = nt * 8 + tg * 2;
                    sG[lr * 33 + col]           = C[nt][0] + sR[lr * 33 + col];
                    sG[lr * 33 + col + 1]       = C[nt][1] + sR[lr * 33 + col + 1];
                    sG[(lr + 8) * 33 + col]     = C[nt][2] + sR[(lr + 8) * 33 + col];
                    sG[(lr + 8) * 33 + col + 1] = C[nt][3] + sR[(lr + 8) * 33 + col + 1];
                }
            }
            __syncthreads();
        }

        // epilogue
        const float* xg = d_xg + (size_t)(dir * TT + t) * 3200 * BB;
        float2 xv0 = *(const float2*)(xg + (size_t)(0 * HH + u) * BB + b0);
        float2 xv1 = *(const float2*)(xg + (size_t)(1 * HH + u) * BB + b0);
        float2 xv2 = *(const float2*)(xg + (size_t)(2 * HH + u) * BB + b0);
        float2 xv3 = *(const float2*)(xg + (size_t)(3 * HH + u) * BB + b0);
        float hv[2];
        #pragma unroll
        for (int i = 0; i < 2; i++) {
            int b = b0 + i;
            float p0 = (i == 0) ? xv0.x : xv0.y;
            float p1 = (i == 0) ? xv1.x : xv1.y;
            float p2 = (i == 0) ? xv2.x : xv2.y;
            float p3 = (i == 0) ? xv3.x : xv3.y;
            if (s > 0) {
                p0 += sG[(ul * 4 + 0) * 33 + b];
                p1 += sG[(ul * 4 + 1) * 33 + b];
                p2 += sG[(ul * 4 + 2) * 33 + b];
                p3 += sG[(ul * 4 + 3) * 33 + b];
            }
            float ig = 1.f / (1.f + expf(-p0));
            float fg = 1.f / (1.f + expf(-p1));
            float gg = tanhf(p2);
            float og = 1.f / (1.f + expf(-p3));
            cs[i] = (s == 0) ? (ig * gg) : (fg * cs[i] + ig * gg);
            hv[i] = og * tanhf(cs[i]);
        }
        if (LAYER == 1) {
            float2 hq = {hv[0], hv[1]};
            *(float2*)(d_h1T + (size_t)t * (K1 * BB) + (size_t)(dir * HH + u) * BB + b0) = hq;
        }

        // fragment-packed h: Bpack (next step) and, for layer 0, d_h0P[t] (for k_xgmma)
        __nv_bfloat16* Bo = (__nv_bfloat16*)d_Bpack[(s + 1) & 1][dir];
        __nv_bfloat16* Po = (__nv_bfloat16*)(d_h0P + (size_t)t * (100 * 4 * 32 * 4));
        #pragma unroll
        for (int i = 0; i < 2; i++) {
            int b = b0 + i;
            int nt = b >> 3;
            int lane2 = (b & 7) * 4 + tg2;
            __nv_bfloat16 hi = __float2bfloat16(hv[i]);
            __nv_bfloat16 lo = __float2bfloat16(hv[i] - __bfloat162float(hi));
            size_t base = ((size_t)(kc2 * 4 + nt) * 32 + lane2) * 4;
            Bo[(base + ri2) * 2 + hh2]     = hi;
            Bo[(base + 2 + ri2) * 2 + hh2] = lo;
            if (LAYER == 0) {
                size_t baseg = ((size_t)((dir * 50 + kc2) * 4 + nt) * 32 + lane2) * 4;
                Po[(baseg + ri2) * 2 + hh2]     = hi;
                Po[(baseg + 2 + ri2) * 2 + hh2] = lo;
            }
        }
    }
}

// ---------------- fc + softmax + dihedral ----------------
__global__ void k_fc(const float* __restrict__ fcW, const float* __restrict__ fcb,
                     const float* __restrict__ alphabet)
{
    const int t = blockIdx.x;
    __shared__ float sbuf[256 * BB];
    __shared__ float slog[AA * 33];
    const int tid = threadIdx.x, warp = tid >> 5, lane = tid & 31;

    float acc[8];
    #pragma unroll
    for (int j = 0; j < 8; j++) { int a = warp * 8 + j; acc[j] = (a < AA) ? fcb[a] : 0.f; }

    for (int chunk = 0; chunk < RNN_OUT; chunk += 256) {
        int nk = min(256, RNN_OUT - chunk);
        for (int i = tid; i < nk * BB; i += blockDim.x) {
            int r = chunk + (i >> 5), b = i & 31;
            sbuf[i] = (r < K1) ? d_h1T[(size_t)t * K1 * BB + (size_t)r * BB + b]
                               : d_xT[(size_t)t * 64 * BB + (size_t)(r - K1) * BB + b];
        }
        __syncthreads();
        #pragma unroll
        for (int j = 0; j < 8; j++) {
            int a = warp * 8 + j;
            if (a < AA) {
                const float* wr = fcW + (size_t)a * RNN_OUT + chunk;
                float aj = acc[j];
                for (int k = 0; k < nk; k++) aj = fmaf(__ldg(wr + k), sbuf[k * BB + lane], aj);
                acc[j] = aj;
            }
        }
        __syncthreads();
    }
    #pragma unroll
    for (int j = 0; j < 8; j++) { int a = warp * 8 + j; if (a < AA) slog[a * 33 + lane] = acc[j]; }
    __syncthreads();

    if (tid < BB) {
        int b = tid;
        float mx = -1e30f;
        for (int a = 0; a < AA; a++) mx = fmaxf(mx, slog[a * 33 + b]);
        float sum = 0.f;
        for (int a = 0; a < AA; a++) { float e = expf(slog[a * 33 + b] - mx); slog[a * 33 + b] = e; sum += e; }
        float inv = 1.f / sum;
        float ss0 = 0, ss1 = 0, ss2 = 0, cc0 = 0, cc1 = 0, cc2 = 0;
        for (int a = 0; a < AA; a++) {
            float p = slog[a * 33 + b] * inv;
            float l0 = alphabet[a * 3 + 0], l1 = alphabet[a * 3 + 1], l2 = alphabet[a * 3 + 2];
            ss0 = fmaf(p, sinf(l0), ss0); cc0 = fmaf(p, cosf(l0), cc0);
            ss1 = fmaf(p, sinf(l1), ss1); cc1 = fmaf(p, cosf(l1), cc1);
            ss2 = fmaf(p, sinf(l2), ss2); cc2 = fmaf(p, cosf(l2), cc2);
        }
        d_dih[(t * BB + b) * 3 + 0] = atan2f(ss0, cc0);
        d_dih[(t * BB + b) * 3 + 1] = atan2f(ss1, cc1);
        d_dih[(t * BB + b) * 3 + 2] = atan2f(ss2, cc2);
    }
}

// ---------------- NeRF chain ----------------
struct V3 { float x, y, z; };
__device__ __forceinline__ V3 v3sub(V3 a, V3 b) { return {a.x - b.x, a.y - b.y, a.z - b.z}; }
__device__ __forceinline__ V3 v3cross(V3 a, V3 b) {
    return {a.y * b.z - a.z * b.y, a.z * b.x - a.x * b.z, a.x * b.y - a.y * b.x};
}
__device__ __forceinline__ V3 v3norm(V3 a) {
    float inv = 1.f / sqrtf(a.x * a.x + a.y * a.y + a.z * a.z + 1e-12f);
    return {a.x * inv, a.y * inv, a.z * inv};
}
__global__ void k_nerf(float* __restrict__ out)
{
    int b = threadIdx.x;
    if (b >= BB) return;
    V3 A  = {-0.70710678118654752f, 1.22474487139158905f, 0.f};
    V3 Bv = {-1.41421356237309505f, 0.f, 0.f};
    V3 C  = {0.f, 0.f, 0.f};
    const float bl[3] = {145.801f, 152.326f, 132.868f};
    const float ba[3] = {2.124f, 1.941f, 2.028f};
    float rct[3], rst[3];
    #pragma unroll
    for (int j = 0; j < 3; j++) {
        float th = 3.14159265358979323846f - ba[j];
        rct[j] = bl[j] * cosf(th);
        rst[j] = bl[j] * sinf(th);
    }
    for (int t = 0; t < TT; t++) {
        #pragma unroll
        for (int j = 0; j < 3; j++) {
            float phi = d_dih[(t * BB + b) * 3 + j];
            V3 p = {rct[j], cosf(phi) * rst[j], sinf(phi) * rst[j]};
            V3 bc = v3norm(v3sub(C, Bv));
            V3 n  = v3norm(v3cross(v3sub(Bv, A), bc));
            V3 nx = v3cross(n, bc);
            V3 co = {C.x + p.x * bc.x + p.y * nx.x + p.z * n.x,
                     C.y + p.x * bc.y + p.y * nx.y + p.z * n.y,
                     C.z + p.x * bc.z + p.y * nx.z + p.z * n.z};
            size_t o = ((size_t)(3 * t + j) * BB + b) * 3;
            out[o + 0] = co.x; out[o + 1] = co.y; out[o + 2] = co.z;
            A = Bv; Bv = C; C = co;
        }
    }
}

// ---------------- launch ----------------
extern "C" void kernel_launch(void* const* d_in, const int* in_sizes, int n_in,
                              void* d_out, int out_size)
{
    int base = 2;
    if (base < n_in && in_sizes[base] == 1) base = 3;

    const int*   primary = (const int*)  d_in[0];
    const float* evo     = (const float*)d_in[1];
    const float* emb     = (const float*)d_in[base + 0];
    const float* Wih0f   = (const float*)d_in[base + 1];
    const float* Whh0f   = (const float*)d_in[base + 2];
    const float* b0f     = (const float*)d_in[base + 3];
    const float* Wih0b   = (const float*)d_in[base + 4];
    const float* Whh0b   = (const float*)d_in[base + 5];
    const float* b0b     = (const float*)d_in[base + 6];
    const float* Wih1f   = (const float*)d_in[base + 7];
    const float* Whh1f   = (const float*)d_in[base + 8];
    const float* b1f     = (const float*)d_in[base + 9];
    const float* Wih1b   = (const float*)d_in[base + 10];
    const float* Whh1b   = (const float*)d_in[base + 11];
    const float* b1b     = (const float*)d_in[base + 12];
    const float* fcW     = (const float*)d_in[base + 13];
    const float* fcb     = (const float*)d_in[base + 14];
    const float* alphabet= (const float*)d_in[base + 15];

    cudaFuncSetAttribute(k_rec<0>, cudaFuncAttributeMaxDynamicSharedMemorySize, SMEM_REC);
    cudaFuncSetAttribute(k_rec<1>, cudaFuncAttributeMaxDynamicSharedMemorySize, SMEM_REC);

    k_prep<<<(TT * 64 * BB + 255) / 256, 256>>>(primary, evo, emb);
    k_trans<<<256, 256>>>(Wih0f, Wih0b);
    k_wconv<<<1024, 256>>>(Whh0f, Whh0b, Whh1f, Whh1b, Wih1f, Wih1b);

    dim3 gxg0(TT, 2, 1);
    k_xg0<<<gxg0, 256, DINX * BB * sizeof(float)>>>(b0f, b0b);
    k_rec<0><<<RGRID, 256, SMEM_REC>>>();
    dim3 gmm(TT, 25, 2);
    k_xgmma<<<gmm, 128>>>(b1f, b1b);
    k_rec<1><<<RGRID, 256, SMEM_REC>>>();

    k_fc<<<TT, 256>>>(fcW, fcb, alphabet);
    k_nerf<<<1, 32>>>((float*)d_out);
}

// round 16
// speedup vs baseline: 4.6147x; 1.0924x over previous
#include <cuda_runtime.h>
#include <cuda_bf16.h>
#include <math.h>
#include <stdint.h>

#define TT 700
#define BB 32
#define HH 800
#define K1 1600
#define DINX 53
#define AA 60
#define RNN_OUT 1653
#define RGRID 100

// ---------------- static device buffers ----------------
__device__ float d_xT [TT * 64 * BB];
__device__ float d_h1T[(size_t)TT * K1 * BB];
__device__ float d_xg [(size_t)2 * TT * 3200 * BB];
__device__ float d_Wt0f[DINX * 3200];
__device__ float d_Wt0b[DINX * 3200];
__device__ float d_dih[TT * BB * 3];
// Whh fragments: [layer][dir][wt 0..199][kc 0..49][lane][q 0..7] (q: 4 hi regs, 4 lo regs)
__device__ __align__(16) uint32_t d_Apack[(size_t)2 * 2 * 200 * 50 * 32 * 8];
// Wih1 fragments: [dir][wt 0..199][kc 0..99][lane][q 0..7]
__device__ __align__(16) uint32_t d_Ain1[(size_t)2 * 200 * 100 * 32 * 8];
// B (=h) fragment-packed for recurrent step: [parity][dir][kc 0..49][nt 0..3][lane][4]
__device__ __align__(16) uint32_t d_Bpack[2][2][50 * 4 * 32 * 4];
// h0 fragment-packed per t for k_xgmma: [t][kc 0..99][nt 0..3][lane][4]
__device__ __align__(16) uint32_t d_h0P[(size_t)TT * 100 * 4 * 32 * 4];

// per-direction grid barrier (zero-init)
__device__ unsigned g_cnt2[2][8];
__device__ unsigned g_master2[2];
__device__ volatile unsigned g_gen3[2];

// ---------------- mma.sync helper ----------------
__device__ __forceinline__ void mma16816(float& d0, float& d1, float& d2, float& d3,
                                         uint32_t a0, uint32_t a1, uint32_t a2, uint32_t a3,
                                         uint32_t b0, uint32_t b1)
{
    asm volatile("mma.sync.aligned.m16n8k16.row.col.f32.bf16.bf16.f32 "
                 "{%0,%1,%2,%3},{%4,%5,%6,%7},{%8,%9},{%0,%1,%2,%3};"
                 : "+f"(d0), "+f"(d1), "+f"(d2), "+f"(d3)
                 : "r"(a0), "r"(a1), "r"(a2), "r"(a3), "r"(b0), "r"(b1));
}

// ---------------- prep ----------------
__global__ void k_prep(const int* __restrict__ primary, const float* __restrict__ evo,
                       const float* __restrict__ emb)
{
    int idx = blockIdx.x * blockDim.x + threadIdx.x;
    if (idx >= TT * 64 * BB) return;
    int b = idx & 31, k = (idx >> 5) & 63, t = idx >> 11;
    float v = 0.f;
    if (k < 32) v = emb[primary[t * BB + b] * 32 + k];
    else if (k < DINX) v = evo[(t * BB + b) * 21 + (k - 32)];
    d_xT[idx] = v;
}

// ---------------- transpose layer-0 input weights [row][k]->[k][row] ----------------
__global__ void k_trans(const float* __restrict__ W0f, const float* __restrict__ W0b)
{
    const int N0 = 3200 * DINX;
    for (int i = blockIdx.x * blockDim.x + threadIdx.x; i < 2 * N0; i += gridDim.x * blockDim.x) {
        if (i < N0) { int r = i / DINX, k = i % DINX; d_Wt0f[k * 3200 + r] = W0f[i]; }
        else { int j2 = i - N0; int r = j2 / DINX, k = j2 % DINX; d_Wt0b[k * 3200 + r] = W0b[j2]; }
    }
}

// ---------------- pack Whh (both layers) + Wih1 into MMA A-fragment order ----------------
__global__ void k_wconv(const float* __restrict__ Whh0f, const float* __restrict__ Whh0b,
                        const float* __restrict__ Whh1f, const float* __restrict__ Whh1b,
                        const float* __restrict__ Wih1f, const float* __restrict__ Wih1b)
{
    const size_t NT1 = (size_t)2 * 2 * 200 * 50 * 32 * 8;
    for (size_t i = (size_t)blockIdx.x * blockDim.x + threadIdx.x; i < NT1;
         i += (size_t)gridDim.x * blockDim.x) {
        int q = (int)(i & 7);
        size_t r = i >> 3;
        int lane = (int)(r & 31); r >>= 5;
        int kc = (int)(r % 50); r /= 50;
        int wt = (int)(r % 200); r /= 200;
        int dir = (int)(r & 1);
        int layer = (int)(r >> 1);
        int ri = q & 3, pass = q >> 2;
        int gid = lane >> 2, tg = lane & 3;
        int p = wt * 16 + gid + (ri & 1) * 8;
        int u = p >> 2, g = p & 3;
        const float* W = layer ? (dir ? Whh1b : Whh1f) : (dir ? Whh0b : Whh0f);
        const float* wr = W + (size_t)(g * HH + u) * HH;
        uint32_t out = 0;
        #pragma unroll
        for (int hh = 0; hh < 2; hh++) {
            int k = kc * 16 + tg * 2 + hh + ((ri >> 1) & 1) * 8;
            float v = wr[k];
            __nv_bfloat16 hi = __float2bfloat16(v);
            __nv_bfloat16 bv = (pass == 0) ? hi : __float2bfloat16(v - __bfloat162float(hi));
            uint16_t bits = *(uint16_t*)&bv;
            out |= (uint32_t)bits << (hh * 16);
        }
        d_Apack[i] = out;
    }
    const size_t NT2 = (size_t)2 * 200 * 100 * 32 * 8;
    for (size_t i = (size_t)blockIdx.x * blockDim.x + threadIdx.x; i < NT2;
         i += (size_t)gridDim.x * blockDim.x) {
        int q = (int)(i & 7);
        size_t r = i >> 3;
        int lane = (int)(r & 31); r >>= 5;
        int kc = (int)(r % 100); r /= 100;
        int wt = (int)(r % 200); r /= 200;
        int dir = (int)r;
        int ri = q & 3, pass = q >> 2;
        int gid = lane >> 2, tg = lane & 3;
        int p = wt * 16 + gid + (ri & 1) * 8;
        int u = p >> 2, g = p & 3;
        const float* W = dir ? Wih1b : Wih1f;
        const float* wr = W + (size_t)(g * HH + u) * K1;
        uint32_t out = 0;
        #pragma unroll
        for (int hh = 0; hh < 2; hh++) {
            int k = kc * 16 + tg * 2 + hh + ((ri >> 1) & 1) * 8;
            float v = wr[k];
            __nv_bfloat16 hi = __float2bfloat16(v);
            __nv_bfloat16 bv = (pass == 0) ? hi : __float2bfloat16(v - __bfloat162float(hi));
            uint16_t bits = *(uint16_t*)&bv;
            out |= (uint32_t)bits << (hh * 16);
        }
        d_Ain1[i] = out;
    }
}

// ---------------- layer-0 xg (scalar, K=53; small) ----------------
__global__ void k_xg0(const float* __restrict__ bF, const float* __restrict__ bB)
{
    extern __shared__ float sx[];
    const int t = blockIdx.x;
    const int dir = blockIdx.y;
    const float* Wt   = dir ? d_Wt0b : d_Wt0f;
    const float* bias = dir ? bB : bF;
    const float* s0 = d_xT + (size_t)t * 64 * BB;

    for (int i = threadIdx.x; i < DINX * BB / 4; i += blockDim.x)
        ((float4*)sx)[i] = ((const float4*)s0)[i];
    __syncthreads();

    float* out = d_xg + (size_t)(dir * TT + t) * 3200 * BB;
    for (int r = threadIdx.x; r < 3200; r += blockDim.x) {
        float acc[32];
        #pragma unroll
        for (int j = 0; j < 32; j++) acc[j] = 0.f;
        const float* wp = Wt + r;
        for (int k = 0; k < DINX; k++) {
            float w = wp[(size_t)k * 3200];
            const float4* xv = (const float4*)(sx + k * 32);
            #pragma unroll
            for (int j = 0; j < 8; j++) {
                float4 v = xv[j];
                acc[4 * j + 0] = fmaf(w, v.x, acc[4 * j + 0]);
                acc[4 * j + 1] = fmaf(w, v.y, acc[4 * j + 1]);
                acc[4 * j + 2] = fmaf(w, v.z, acc[4 * j + 2]);
                acc[4 * j + 3] = fmaf(w, v.w, acc[4 * j + 3]);
            }
        }
        float bv = bias[r];
        float4* op = (float4*)(out + (size_t)r * BB);
        #pragma unroll
        for (int j = 0; j < 8; j++) {
            float4 v4 = {acc[4*j+0] + bv, acc[4*j+1] + bv, acc[4*j+2] + bv, acc[4*j+3] + bv};
            op[j] = v4;
        }
    }
}

// ---------------- layer-1 xg via mma.sync, 2 timesteps per block ----------------
__global__ void __launch_bounds__(128, 1) k_xgmma(const float* __restrict__ b1f,
                                                  const float* __restrict__ b1b)
{
    const int t0 = blockIdx.x * 2;
    const int mt = blockIdx.y;
    const int dir = blockIdx.z;
    const int w = threadIdx.x >> 5, lane = threadIdx.x & 31;
    const int gid = lane >> 2, tg = lane & 3;
    const float* bias = dir ? b1b : b1f;

    const uint4* Bb0 = (const uint4*)d_h0P + (size_t)t0 * (100 * 4 * 32);
    const uint4* Bb1 = Bb0 + (size_t)100 * 4 * 32;
    const int wt0 = mt * 8 + w * 2;
    const uint4* A0 = (const uint4*)d_Ain1 + ((size_t)(dir * 200 + wt0)) * 100 * 32 * 2;
    const uint4* A1 = A0 + (size_t)100 * 32 * 2;

    float C[2][2][4][4];   // [tsub][q][nt][i]
    #pragma unroll
    for (int ts = 0; ts < 2; ts++)
        #pragma unroll
        for (int q = 0; q < 2; q++)
            #pragma unroll
            for (int nt = 0; nt < 4; nt++)
                #pragma unroll
                for (int i = 0; i < 4; i++) C[ts][q][nt][i] = 0.f;

    #pragma unroll 2
    for (int kc = 0; kc < 100; kc++) {
        uint4 a0h = A0[(kc * 32 + lane) * 2];
        uint4 a0l = A0[(kc * 32 + lane) * 2 + 1];
        uint4 a1h = A1[(kc * 32 + lane) * 2];
        uint4 a1l = A1[(kc * 32 + lane) * 2 + 1];
        #pragma unroll
        for (int nt = 0; nt < 4; nt++) {
            uint4 b0 = Bb0[(kc * 4 + nt) * 32 + lane];
            uint4 b1 = Bb1[(kc * 4 + nt) * 32 + lane];
            mma16816(C[0][0][nt][0], C[0][0][nt][1], C[0][0][nt][2], C[0][0][nt][3],
                     a0h.x, a0h.y, a0h.z, a0h.w, b0.x, b0.y);
            mma16816(C[0][0][nt][0], C[0][0][nt][1], C[0][0][nt][2], C[0][0][nt][3],
                     a0l.x, a0l.y, a0l.z, a0l.w, b0.x, b0.y);
            mma16816(C[0][0][nt][0], C[0][0][nt][1], C[0][0][nt][2], C[0][0][nt][3],
                     a0h.x, a0h.y, a0h.z, a0h.w, b0.z, b0.w);
            mma16816(C[0][1][nt][0], C[0][1][nt][1], C[0][1][nt][2], C[0][1][nt][3],
                     a1h.x, a1h.y, a1h.z, a1h.w, b0.x, b0.y);
            mma16816(C[0][1][nt][0], C[0][1][nt][1], C[0][1][nt][2], C[0][1][nt][3],
                     a1l.x, a1l.y, a1l.z, a1l.w, b0.x, b0.y);
            mma16816(C[0][1][nt][0], C[0][1][nt][1], C[0][1][nt][2], C[0][1][nt][3],
                     a1h.x, a1h.y, a1h.z, a1h.w, b0.z, b0.w);
            mma16816(C[1][0][nt][0], C[1][0][nt][1], C[1][0][nt][2], C[1][0][nt][3],
                     a0h.x, a0h.y, a0h.z, a0h.w, b1.x, b1.y);
            mma16816(C[1][0][nt][0], C[1][0][nt][1], C[1][0][nt][2], C[1][0][nt][3],
                     a0l.x, a0l.y, a0l.z, a0l.w, b1.x, b1.y);
            mma16816(C[1][0][nt][0], C[1][0][nt][1], C[1][0][nt][2], C[1][0][nt][3],
                     a0h.x, a0h.y, a0h.z, a0h.w, b1.z, b1.w);
            mma16816(C[1][1][nt][0], C[1][1][nt][1], C[1][1][nt][2], C[1][1][nt][3],
                     a1h.x, a1h.y, a1h.z, a1h.w, b1.x, b1.y);
            mma16816(C[1][1][nt][0], C[1][1][nt][1], C[1][1][nt][2], C[1][1][nt][3],
                     a1l.x, a1l.y, a1l.z, a1l.w, b1.x, b1.y);
            mma16816(C[1][1][nt][0], C[1][1][nt][1], C[1][1][nt][2], C[1][1][nt][3],
                     a1h.x, a1h.y, a1h.z, a1h.w, b1.z, b1.w);
        }
    }

    #pragma unroll
    for (int ts = 0; ts < 2; ts++) {
        float* out = d_xg + (size_t)(dir * TT + (t0 + ts)) * 3200 * BB;
        #pragma unroll
        for (int q = 0; q < 2; q++) {
            int wt = wt0 + q;
            #pragma unroll
            for (int half = 0; half < 2; half++) {
                int p = wt * 16 + gid + half * 8;
                int u = p >> 2, g = p & 3;
                int r = g * HH + u;
                float bv = __ldg(bias + r);
                float* orow = out + (size_t)r * BB;
                #pragma unroll
                for (int nt = 0; nt < 4; nt++) {
                    int col = nt * 8 + tg * 2;
                    float2 v = {C[ts][q][nt][half * 2 + 0] + bv, C[ts][q][nt][half * 2 + 1] + bv};
                    *(float2*)(orow + col) = v;
                }
            }
        }
    }
}

// ---------------- per-direction 50-CTA barrier (nanosleep backoff) ----------------
__device__ __forceinline__ void gsync50(int dir, unsigned& mygen)
{
    __syncthreads();
    if (threadIdx.x == 0) {
        __threadfence();
        int grp = (blockIdx.x >> 1) & 7;          // jt-based group
        unsigned sz = (grp < 2) ? 7u : 6u;        // 50 = 2*7 + 6*6
        unsigned v = atomicAdd(&g_cnt2[dir][grp], 1u);
        if (v == sz - 1u) {
            g_cnt2[dir][grp] = 0u;
            __threadfence();
            unsigned m = atomicAdd(&g_master2[dir], 1u);
            if (m == 7u) {
                g_master2[dir] = 0u;
                __threadfence();
                g_gen3[dir] = mygen + 1u;
            }
        }
        while (g_gen3[dir] == mygen) { __nanosleep(32); }
        __threadfence();
    }
    __syncthreads();
    mygen++;
}

// ---------------- persistent mma.sync recurrent layer (split-K, 8 warps, smem-resident A) ----------------
#define SMA_BYTES 204800
#define SMEM_REC (SMA_BYTES + 2 * 64 * 33 * 4)

template <int LAYER>
__global__ void __launch_bounds__(256, 1) k_rec()
{
    extern __shared__ __align__(16) unsigned char smrec[];
    uint4* smA = (uint4*)smrec;
    float* sG = (float*)(smrec + SMA_BYTES);
    float* sR = sG + 64 * 33;

    const int tid = threadIdx.x;
    const int w = tid >> 5, lane = tid & 31;
    const int dir = blockIdx.x & 1;
    const int jt = blockIdx.x >> 1;
    const int wtl = w & 3;
    const int kh = w >> 2;
    const int gid = lane >> 2, tg = lane & 3;

    // load this CTA's A slice once (4 wt contiguous in d_Apack)
    {
        const uint4* Asrc = (const uint4*)d_Apack
            + ((size_t)((LAYER * 2 + dir) * 200 + jt * 4)) * 50 * 32 * 2;
        for (int i = tid; i < 4 * 50 * 32 * 2; i += 256) smA[i] = Asrc[i];
    }
    __syncthreads();

    const uint4* Aw = smA + ((size_t)(wtl * 50 + kh * 25)) * 32 * 2;

    // epilogue mapping: thread -> (unit u, batches b0..b0+1)
    const int ul = tid >> 4;
    const int b0 = (tid & 15) * 2;
    const int u = jt * 16 + ul;
    const int kc2 = u >> 4, kl = u & 15;
    const int ri2 = kl >> 3, rem = kl & 7, tg2 = rem >> 1, hh2 = rem & 1;

    unsigned mygen = g_gen3[dir];
    float cs[2] = {0.f, 0.f};

    for (int s = 0; s < TT; s++) {
        const int t = dir ? (TT - 1 - s) : s;

        // prefetch epilogue xg loads BEFORE the barrier (DRAM latency hidden by wait)
        const float* xg = d_xg + (size_t)(dir * TT + t) * 3200 * BB;
        float2 xv0 = *(const float2*)(xg + (size_t)(0 * HH + u) * BB + b0);
        float2 xv1 = *(const float2*)(xg + (size_t)(1 * HH + u) * BB + b0);
        float2 xv2 = *(const float2*)(xg + (size_t)(2 * HH + u) * BB + b0);
        float2 xv3 = *(const float2*)(xg + (size_t)(3 * HH + u) * BB + b0);

        if (s > 0) {
            gsync50(dir, mygen);
            const uint4* Bb = (const uint4*)d_Bpack[s & 1][dir] + (size_t)kh * 25 * 4 * 32;
            float C[4][4];
            #pragma unroll
            for (int nt = 0; nt < 4; nt++)
                #pragma unroll
                for (int i = 0; i < 4; i++) C[nt][i] = 0.f;

            // double-buffered B
            uint4 bc[4];
            #pragma unroll
            for (int nt = 0; nt < 4; nt++) bc[nt] = Bb[nt * 32 + lane];

            #pragma unroll 5
            for (int kc = 0; kc < 25; kc++) {
                uint4 bn[4];
                #pragma unroll
                for (int nt = 0; nt < 4; nt++) bn[nt] = bc[nt];
                if (kc < 24) {
                    #pragma unroll
                    for (int nt = 0; nt < 4; nt++) bn[nt] = Bb[((kc + 1) * 4 + nt) * 32 + lane];
                }
                uint4 ahi = Aw[(kc * 32 + lane) * 2];
                uint4 alo = Aw[(kc * 32 + lane) * 2 + 1];
                #pragma unroll
                for (int nt = 0; nt < 4; nt++) {
                    mma16816(C[nt][0], C[nt][1], C[nt][2], C[nt][3],
                             ahi.x, ahi.y, ahi.z, ahi.w, bc[nt].x, bc[nt].y);
                    mma16816(C[nt][0], C[nt][1], C[nt][2], C[nt][3],
                             alo.x, alo.y, alo.z, alo.w, bc[nt].x, bc[nt].y);
                    mma16816(C[nt][0], C[nt][1], C[nt][2], C[nt][3],
                             ahi.x, ahi.y, ahi.z, ahi.w, bc[nt].z, bc[nt].w);
                }
                #pragma unroll
                for (int nt = 0; nt < 4; nt++) bc[nt] = bn[nt];
            }
            const int lr = wtl * 16 + gid;
            if (kh == 1) {
                #pragma unroll
                for (int nt = 0; nt < 4; nt++) {
                    int col = nt * 8 + tg * 2;
                    sR[lr * 33 + col]           = C[nt][0];
                    sR[lr * 33 + col + 1]       = C[nt][1];
                    sR[(lr + 8) * 33 + col]     = C[nt][2];
                    sR[(lr + 8) * 33 + col + 1] = C[nt][3];
                }
            }
            __syncthreads();
            if (kh == 0) {
                #pragma unroll
                for (int nt = 0; nt < 4; nt++) {
                    int col = nt * 8 + tg * 2;
                    sG[lr * 33 + col]           = C[nt][0] + sR[lr * 33 + col];
                    sG[lr * 33 + col + 1]       = C[nt][1] + sR[lr * 33 + col + 1];
                    sG[(lr + 8) * 33 + col]     = C[nt][2] + sR[(lr + 8) * 33 + col];
                    sG[(lr + 8) * 33 + col + 1] = C[nt][3] + sR[(lr + 8) * 33 + col + 1];
                }
            }
            __syncthreads();
        }

        // epilogue
        float hv[2];
        #pragma unroll
        for (int i = 0; i < 2; i++) {
            int b = b0 + i;
            float p0 = (i == 0) ? xv0.x : xv0.y;
            float p1 = (i == 0) ? xv1.x : xv1.y;
            float p2 = (i == 0) ? xv2.x : xv2.y;
            float p3 = (i == 0) ? xv3.x : xv3.y;
            if (s > 0) {
                p0 += sG[(ul * 4 + 0) * 33 + b];
                p1 += sG[(ul * 4 + 1) * 33 + b];
                p2 += sG[(ul * 4 + 2) * 33 + b];
                p3 += sG[(ul * 4 + 3) * 33 + b];
            }
            float ig = 1.f / (1.f + expf(-p0));
            float fg = 1.f / (1.f + expf(-p1));
            float gg = tanhf(p2);
            float og = 1.f / (1.f + expf(-p3));
            cs[i] = (s == 0) ? (ig * gg) : (fg * cs[i] + ig * gg);
            hv[i] = og * tanhf(cs[i]);
        }
        if (LAYER == 1) {
            float2 hq = {hv[0], hv[1]};
            *(float2*)(d_h1T + (size_t)t * (K1 * BB) + (size_t)(dir * HH + u) * BB + b0) = hq;
        }

        // fragment-packed h: Bpack (next step) and, for layer 0, d_h0P[t] (for k_xgmma)
        __nv_bfloat16* Bo = (__nv_bfloat16*)d_Bpack[(s + 1) & 1][dir];
        __nv_bfloat16* Po = (__nv_bfloat16*)(d_h0P + (size_t)t * (100 * 4 * 32 * 4));
        #pragma unroll
        for (int i = 0; i < 2; i++) {
            int b = b0 + i;
            int nt = b >> 3;
            int lane2 = (b & 7) * 4 + tg2;
            __nv_bfloat16 hi = __float2bfloat16(hv[i]);
            __nv_bfloat16 lo = __float2bfloat16(hv[i] - __bfloat162float(hi));
            size_t base = ((size_t)(kc2 * 4 + nt) * 32 + lane2) * 4;
            Bo[(base + ri2) * 2 + hh2]     = hi;
            Bo[(base + 2 + ri2) * 2 + hh2] = lo;
            if (LAYER == 0) {
                size_t baseg = ((size_t)((dir * 50 + kc2) * 4 + nt) * 32 + lane2) * 4;
                Po[(baseg + ri2) * 2 + hh2]     = hi;
                Po[(baseg + 2 + ri2) * 2 + hh2] = lo;
            }
        }
    }
}

// ---------------- fc + softmax + dihedral ----------------
__global__ void k_fc(const float* __restrict__ fcW, const float* __restrict__ fcb,
                     const float* __restrict__ alphabet)
{
    const int t = blockIdx.x;
    __shared__ float sbuf[256 * BB];
    __shared__ float slog[AA * 33];
    const int tid = threadIdx.x, warp = tid >> 5, lane = tid & 31;

    float acc[8];
    #pragma unroll
    for (int j = 0; j < 8; j++) { int a = warp * 8 + j; acc[j] = (a < AA) ? fcb[a] : 0.f; }

    for (int chunk = 0; chunk < RNN_OUT; chunk += 256) {
        int nk = min(256, RNN_OUT - chunk);
        for (int i = tid; i < nk * BB; i += blockDim.x) {
            int r = chunk + (i >> 5), b = i & 31;
            sbuf[i] = (r < K1) ? d_h1T[(size_t)t * K1 * BB + (size_t)r * BB + b]
                               : d_xT[(size_t)t * 64 * BB + (size_t)(r - K1) * BB + b];
        }
        __syncthreads();
        #pragma unroll
        for (int j = 0; j < 8; j++) {
            int a = warp * 8 + j;
            if (a < AA) {
                const float* wr = fcW + (size_t)a * RNN_OUT + chunk;
                float aj = acc[j];
                for (int k = 0; k < nk; k++) aj = fmaf(__ldg(wr + k), sbuf[k * BB + lane], aj);
                acc[j] = aj;
            }
        }
        __syncthreads();
    }
    #pragma unroll
    for (int j = 0; j < 8; j++) { int a = warp * 8 + j; if (a < AA) slog[a * 33 + lane] = acc[j]; }
    __syncthreads();

    if (tid < BB) {
        int b = tid;
        float mx = -1e30f;
        for (int a = 0; a < AA; a++) mx = fmaxf(mx, slog[a * 33 + b]);
        float sum = 0.f;
        for (int a = 0; a < AA; a++) { float e = expf(slog[a * 33 + b] - mx); slog[a * 33 + b] = e; sum += e; }
        float inv = 1.f / sum;
        float ss0 = 0, ss1 = 0, ss2 = 0, cc0 = 0, cc1 = 0, cc2 = 0;
        for (int a = 0; a < AA; a++) {
            float p = slog[a * 33 + b] * inv;
            float l0 = alphabet[a * 3 + 0], l1 = alphabet[a * 3 + 1], l2 = alphabet[a * 3 + 2];
            ss0 = fmaf(p, sinf(l0), ss0); cc0 = fmaf(p, cosf(l0), cc0);
            ss1 = fmaf(p, sinf(l1), ss1); cc1 = fmaf(p, cosf(l1), cc1);
            ss2 = fmaf(p, sinf(l2), ss2); cc2 = fmaf(p, cosf(l2), cc2);
        }
        d_dih[(t * BB + b) * 3 + 0] = atan2f(ss0, cc0);
        d_dih[(t * BB + b) * 3 + 1] = atan2f(ss1, cc1);
        d_dih[(t * BB + b) * 3 + 2] = atan2f(ss2, cc2);
    }
}

// ---------------- NeRF chain ----------------
struct V3 { float x, y, z; };
__device__ __forceinline__ V3 v3sub(V3 a, V3 b) { return {a.x - b.x, a.y - b.y, a.z - b.z}; }
__device__ __forceinline__ V3 v3cross(V3 a, V3 b) {
    return {a.y * b.z - a.z * b.y, a.z * b.x - a.x * b.z, a.x * b.y - a.y * b.x};
}
__device__ __forceinline__ V3 v3norm(V3 a) {
    float inv = 1.f / sqrtf(a.x * a.x + a.y * a.y + a.z * a.z + 1e-12f);
    return {a.x * inv, a.y * inv, a.z * inv};
}
__global__ void k_nerf(float* __restrict__ out)
{
    int b = threadIdx.x;
    if (b >= BB) return;
    V3 A  = {-0.70710678118654752f, 1.22474487139158905f, 0.f};
    V3 Bv = {-1.41421356237309505f, 0.f, 0.f};
    V3 C  = {0.f, 0.f, 0.f};
    const float bl[3] = {145.801f, 152.326f, 132.868f};
    const float ba[3] = {2.124f, 1.941f, 2.028f};
    float rct[3], rst[3];
    #pragma unroll
    for (int j = 0; j < 3; j++) {
        float th = 3.14159265358979323846f - ba[j];
        rct[j] = bl[j] * cosf(th);
        rst[j] = bl[j] * sinf(th);
    }
    for (int t = 0; t < TT; t++) {
        #pragma unroll
        for (int j = 0; j < 3; j++) {
            float phi = d_dih[(t * BB + b) * 3 + j];
            V3 p = {rct[j], cosf(phi) * rst[j], sinf(phi) * rst[j]};
            V3 bc = v3norm(v3sub(C, Bv));
            V3 n  = v3norm(v3cross(v3sub(Bv, A), bc));
            V3 nx = v3cross(n, bc);
            V3 co = {C.x + p.x * bc.x + p.y * nx.x + p.z * n.x,
                     C.y + p.x * bc.y + p.y * nx.y + p.z * n.y,
                     C.z + p.x * bc.z + p.y * nx.z + p.z * n.z};
            size_t o = ((size_t)(3 * t + j) * BB + b) * 3;
            out[o + 0] = co.x; out[o + 1] = co.y; out[o + 2] = co.z;
            A = Bv; Bv = C; C = co;
        }
    }
}

// ---------------- launch ----------------
extern "C" void kernel_launch(void* const* d_in, const int* in_sizes, int n_in,
                              void* d_out, int out_size)
{
    int base = 2;
    if (base < n_in && in_sizes[base] == 1) base = 3;

    const int*   primary = (const int*)  d_in[0];
    const float* evo     = (const float*)d_in[1];
    const float* emb     = (const float*)d_in[base + 0];
    const float* Wih0f   = (const float*)d_in[base + 1];
    const float* Whh0f   = (const float*)d_in[base + 2];
    const float* b0f     = (const float*)d_in[base + 3];
    const float* Wih0b   = (const float*)d_in[base + 4];
    const float* Whh0b   = (const float*)d_in[base + 5];
    const float* b0b     = (const float*)d_in[base + 6];
    const float* Wih1f   = (const float*)d_in[base + 7];
    const float* Whh1f   = (const float*)d_in[base + 8];
    const float* b1f     = (const float*)d_in[base + 9];
    const float* Wih1b   = (const float*)d_in[base + 10];
    const float* Whh1b   = (const float*)d_in[base + 11];
    const float* b1b     = (const float*)d_in[base + 12];
    const float* fcW     = (const float*)d_in[base + 13];
    const float* fcb     = (const float*)d_in[base + 14];
    const float* alphabet= (const float*)d_in[base + 15];

    cudaFuncSetAttribute(k_rec<0>, cudaFuncAttributeMaxDynamicSharedMemorySize, SMEM_REC);
    cudaFuncSetAttribute(k_rec<1>, cudaFuncAttributeMaxDynamicSharedMemorySize, SMEM_REC);

    k_prep<<<(TT * 64 * BB + 255) / 256, 256>>>(primary, evo, emb);
    k_trans<<<256, 256>>>(Wih0f, Wih0b);
    k_wconv<<<1024, 256>>>(Whh0f, Whh0b, Whh1f, Whh1b, Wih1f, Wih1b);

    dim3 gxg0(TT, 2, 1);
    k_xg0<<<gxg0, 256, DINX * BB * sizeof(float)>>>(b0f, b0b);
    k_rec<0><<<RGRID, 256, SMEM_REC>>>();
    dim3 gmm(350, 25, 2);
    k_xgmma<<<gmm, 128>>>(b1f, b1b);
    k_rec<1><<<RGRID, 256, SMEM_REC>>>();

    k_fc<<<TT, 256>>>(fcW, fcb, alphabet);
    k_nerf<<<1, 32>>>((float*)d_out);
}